// round 1
// baseline (speedup 1.0000x reference)
#include <cuda_runtime.h>
#include <cuda_fp16.h>

#define SEQ    3072
#define HID    1280
#define NHEAD  16
#define HD     80
#define SEGLEN 512
#define NSEG   6
#define QKVN   3840

// ---------------- scratch (no allocations allowed) ----------------
__device__ float  g_qkv[SEQ * QKVN];           // 47 MB  qkv fp32
__device__ __half g_q[NHEAD * SEQ * HD];       // [h][s][d]
__device__ __half g_k[NHEAD * SEQ * HD];
__device__ __half g_v[NHEAD * SEQ * HD];
__device__ float  g_attn[SEQ * HID];           // attention output (fp16-rounded values)

// ---------------- fp32 SGEMM: C[M,N] = A[M,K] * B[N,K]^T + bias[N] ----------------
// BM=BN=128, BK=8, 256 threads, 8x8 per-thread microtile.
__global__ __launch_bounds__(256) void sgemm_nt(
    const float* __restrict__ A, const float* __restrict__ B,
    const float* __restrict__ bias, float* __restrict__ C,
    int M, int N, int K)
{
    __shared__ float As[8][128];
    __shared__ float Bs[8][128];

    const int tid = threadIdx.x;
    const int tx = tid & 15;          // 0..15 -> N microtiles
    const int ty = tid >> 4;          // 0..15 -> M microtiles
    const int bm = blockIdx.y * 128;
    const int bn = blockIdx.x * 128;

    const int lr = tid >> 1;          // 0..127 row within tile
    const int lk = (tid & 1) * 4;     // 0 or 4

    const float* Ap = A + (size_t)(bm + lr) * K + lk;
    const float* Bp = B + (size_t)(bn + lr) * K + lk;

    float acc[8][8];
#pragma unroll
    for (int i = 0; i < 8; i++)
#pragma unroll
        for (int j = 0; j < 8; j++) acc[i][j] = 0.0f;

    for (int k0 = 0; k0 < K; k0 += 8) {
        float4 a = *(const float4*)(Ap + k0);
        float4 b = *(const float4*)(Bp + k0);
        As[lk + 0][lr] = a.x; As[lk + 1][lr] = a.y;
        As[lk + 2][lr] = a.z; As[lk + 3][lr] = a.w;
        Bs[lk + 0][lr] = b.x; Bs[lk + 1][lr] = b.y;
        Bs[lk + 2][lr] = b.z; Bs[lk + 3][lr] = b.w;
        __syncthreads();
#pragma unroll
        for (int kk = 0; kk < 8; kk++) {
            float4 a0 = *(const float4*)&As[kk][ty * 8];
            float4 a1 = *(const float4*)&As[kk][ty * 8 + 4];
            float4 b0 = *(const float4*)&Bs[kk][tx * 8];
            float4 b1 = *(const float4*)&Bs[kk][tx * 8 + 4];
            float ar[8] = {a0.x, a0.y, a0.z, a0.w, a1.x, a1.y, a1.z, a1.w};
            float br[8] = {b0.x, b0.y, b0.z, b0.w, b1.x, b1.y, b1.z, b1.w};
#pragma unroll
            for (int i = 0; i < 8; i++)
#pragma unroll
                for (int j = 0; j < 8; j++)
                    acc[i][j] = fmaf(ar[i], br[j], acc[i][j]);
        }
        __syncthreads();
    }

#pragma unroll
    for (int i = 0; i < 8; i++) {
        const int row = bm + ty * 8 + i;
#pragma unroll
        for (int j = 0; j < 8; j += 4) {
            const int col = bn + tx * 8 + j;
            float4 o;
            o.x = acc[i][j + 0] + bias[col + 0];
            o.y = acc[i][j + 1] + bias[col + 1];
            o.z = acc[i][j + 2] + bias[col + 2];
            o.w = acc[i][j + 3] + bias[col + 3];
            *(float4*)&C[(size_t)row * N + col] = o;
        }
    }
}

// ---------------- RoPE + fp16 cast ----------------
// One thread per (s, head, d<40) pair. cos/sin are [SEQ, 80] with the
// two halves identical, so only index d (<40) is needed for both halves.
__global__ __launch_bounds__(256) void rope_cast_kernel(
    const float* __restrict__ qkv,
    const float* __restrict__ cosp, const float* __restrict__ sinp,
    __half* __restrict__ q, __half* __restrict__ k, __half* __restrict__ v)
{
    int idx = blockIdx.x * blockDim.x + threadIdx.x;   // SEQ*NHEAD*40
    if (idx >= SEQ * NHEAD * 40) return;
    int d = idx % 40;
    int h = (idx / 40) % NHEAD;
    int s = idx / (40 * NHEAD);

    float c  = cosp[s * HD + d];
    float sn = sinp[s * HD + d];

    int base = s * QKVN + h * HD + d;
    float q1 = qkv[base],            q2 = qkv[base + 40];
    float k1 = qkv[base + HID],      k2 = qkv[base + HID + 40];
    float v1 = qkv[base + 2 * HID],  v2 = qkv[base + 2 * HID + 40];

    int o = (h * SEQ + s) * HD + d;
    q[o]      = __float2half(q1 * c - q2 * sn);
    q[o + 40] = __float2half(q2 * c + q1 * sn);
    k[o]      = __float2half(k1 * c - k2 * sn);
    k[o + 40] = __float2half(k2 * c + k1 * sn);
    v[o]      = __float2half(v1);
    v[o + 40] = __float2half(v2);
}

// ---------------- attention ----------------
// Block = (head, segment, 128-query chunk). 6 segs * 4 chunks * 16 heads = 384 blocks.
// smem: Qs float[80][128] | KVs float[80*128] (K as [d][r], V as [k][d]) |
//       Ss half[128][512] | mrow/lrow float[128] each
#define ATTN_SMEM (80 * 128 * 4 + 80 * 128 * 4 + 128 * 512 * 2 + 256 * 4)

__global__ __launch_bounds__(256) void attn_kernel(
    const __half* __restrict__ q, const __half* __restrict__ k,
    const __half* __restrict__ v, float* __restrict__ attn_out)
{
    extern __shared__ char smraw[];
    float*  Qs   = (float*)smraw;                 // [80][128]
    float*  KVs  = Qs + 80 * 128;                 // [80][128] (K) / [128][80] (V)
    __half* Ss   = (__half*)(KVs + 80 * 128);     // [128][512]
    float*  mrow = (float*)(Ss + 128 * 512);      // [128]
    float*  lrow = mrow + 128;                    // [128]

    const int tid  = threadIdx.x;
    const int tx   = tid & 15;
    const int ty   = tid >> 4;
    const int h    = blockIdx.y;
    const int seg  = blockIdx.x >> 2;
    const int qc   = blockIdx.x & 3;
    const int qbase = seg * SEGLEN + qc * 128;
    const int kbase = seg * SEGLEN;
    const float scale = 0.11180339887498949f;     // 80^-0.5

    // load Q chunk (transposed to [d][r], converted to fp32)
    for (int i = tid; i < 128 * HD; i += 256) {
        int r = i / HD, d = i % HD;
        Qs[d * 128 + r] = __half2float(q[(size_t)(h * SEQ + qbase + r) * HD + d]);
    }

    // ---- pass 1: scores -> Ss (fp16, scaled) ----
    for (int kt = 0; kt < 4; kt++) {
        __syncthreads();
        for (int i = tid; i < 128 * HD; i += 256) {
            int r = i / HD, d = i % HD;
            KVs[d * 128 + r] =
                __half2float(k[(size_t)(h * SEQ + kbase + kt * 128 + r) * HD + d]);
        }
        __syncthreads();

        float acc[8][8];
#pragma unroll
        for (int i = 0; i < 8; i++)
#pragma unroll
            for (int j = 0; j < 8; j++) acc[i][j] = 0.0f;

        for (int d = 0; d < HD; d++) {
            float4 a0 = *(const float4*)&Qs[d * 128 + ty * 8];
            float4 a1 = *(const float4*)&Qs[d * 128 + ty * 8 + 4];
            float4 b0 = *(const float4*)&KVs[d * 128 + tx * 8];
            float4 b1 = *(const float4*)&KVs[d * 128 + tx * 8 + 4];
            float ar[8] = {a0.x, a0.y, a0.z, a0.w, a1.x, a1.y, a1.z, a1.w};
            float br[8] = {b0.x, b0.y, b0.z, b0.w, b1.x, b1.y, b1.z, b1.w};
#pragma unroll
            for (int i = 0; i < 8; i++)
#pragma unroll
                for (int j = 0; j < 8; j++)
                    acc[i][j] = fmaf(ar[i], br[j], acc[i][j]);
        }

#pragma unroll
        for (int i = 0; i < 8; i++) {
            __half hs[8];
#pragma unroll
            for (int j = 0; j < 8; j++) hs[j] = __float2half(acc[i][j] * scale);
            *(uint4*)&Ss[(ty * 8 + i) * 512 + kt * 128 + tx * 8] = *(uint4*)hs;
        }
    }
    __syncthreads();

    // ---- softmax stats: 8 warps x 16 rows ----
    {
        const int warp = tid >> 5, lane = tid & 31;
        for (int rr = 0; rr < 16; rr++) {
            int r = warp * 16 + rr;
            float m = -1e30f;
            for (int c = lane; c < 512; c += 32)
                m = fmaxf(m, __half2float(Ss[r * 512 + c]));
#pragma unroll
            for (int o = 16; o; o >>= 1)
                m = fmaxf(m, __shfl_xor_sync(0xffffffffu, m, o));
            float l = 0.0f;
            for (int c = lane; c < 512; c += 32)
                l += expf(__half2float(Ss[r * 512 + c]) - m);
#pragma unroll
            for (int o = 16; o; o >>= 1)
                l += __shfl_xor_sync(0xffffffffu, l, o);
            if (lane == 0) { mrow[r] = m; lrow[r] = l; }
        }
    }
    __syncthreads();

    // ---- weights (fp32 softmax, then fp16 like reference) ----
    for (int i = tid; i < 128 * 512; i += 256) {
        int r = i >> 9;
        float w = expf(__half2float(Ss[i]) - mrow[r]) / lrow[r];
        Ss[i] = __float2half(w);
    }

    // ---- pass 2: O = W @ V ----
    float oacc[8][5];
#pragma unroll
    for (int i = 0; i < 8; i++)
#pragma unroll
        for (int j = 0; j < 5; j++) oacc[i][j] = 0.0f;

    for (int kt = 0; kt < 4; kt++) {
        __syncthreads();   // also covers weight-conversion completion on kt==0
        for (int i = tid; i < 128 * HD; i += 256) {
            int r = i / HD, d = i % HD;
            KVs[r * HD + d] =
                __half2float(v[(size_t)(h * SEQ + kbase + kt * 128 + r) * HD + d]);
        }
        __syncthreads();

        for (int kk = 0; kk < 128; kk++) {
            float w[8];
#pragma unroll
            for (int i = 0; i < 8; i++)
                w[i] = __half2float(Ss[(ty * 8 + i) * 512 + kt * 128 + kk]);
#pragma unroll
            for (int j = 0; j < 5; j++) {
                float vv = KVs[kk * HD + tx * 5 + j];
#pragma unroll
                for (int i = 0; i < 8; i++)
                    oacc[i][j] = fmaf(w[i], vv, oacc[i][j]);
            }
        }
    }

    // write, rounded through fp16 (reference attn einsum output is fp16)
#pragma unroll
    for (int i = 0; i < 8; i++) {
        int row = qbase + ty * 8 + i;
#pragma unroll
        for (int j = 0; j < 5; j++) {
            float val = __half2float(__float2half(oacc[i][j]));
            attn_out[(size_t)row * HID + h * HD + tx * 5 + j] = val;
        }
    }
}

// ---------------- launch ----------------
extern "C" void kernel_launch(void* const* d_in, const int* in_sizes, int n_in,
                              void* d_out, int out_size)
{
    const float* hidden = (const float*)d_in[0];
    const float* cosp   = (const float*)d_in[1];
    const float* sinp   = (const float*)d_in[2];
    const float* w_qkv  = (const float*)d_in[3];
    const float* b_qkv  = (const float*)d_in[4];
    const float* w_proj = (const float*)d_in[5];
    const float* b_proj = (const float*)d_in[6];
    float* out = (float*)d_out;

    float *qkv_p, *attn_p;
    __half *q_p, *k_p, *v_p;
    cudaGetSymbolAddress((void**)&qkv_p, g_qkv);
    cudaGetSymbolAddress((void**)&q_p, g_q);
    cudaGetSymbolAddress((void**)&k_p, g_k);
    cudaGetSymbolAddress((void**)&v_p, g_v);
    cudaGetSymbolAddress((void**)&attn_p, g_attn);

    cudaFuncSetAttribute(attn_kernel,
                         cudaFuncAttributeMaxDynamicSharedMemorySize, ATTN_SMEM);

    // 1) QKV GEMM: [3072,1280] x [3840,1280]^T + b
    sgemm_nt<<<dim3(QKVN / 128, SEQ / 128), 256>>>(
        hidden, w_qkv, b_qkv, qkv_p, SEQ, QKVN, HID);

    // 2) RoPE + fp16 cast
    rope_cast_kernel<<<(SEQ * NHEAD * 40) / 256, 256>>>(
        qkv_p, cosp, sinp, q_p, k_p, v_p);

    // 3) block-diagonal attention
    attn_kernel<<<dim3(NSEG * 4, NHEAD), 256, ATTN_SMEM>>>(
        q_p, k_p, v_p, attn_p);

    // 4) output projection: [3072,1280] x [1280,1280]^T + b
    sgemm_nt<<<dim3(HID / 128, SEQ / 128), 256>>>(
        attn_p, w_proj, b_proj, out, SEQ, HID, HID);
}

// round 2
// speedup vs baseline: 1.7621x; 1.7621x over previous
#include <cuda_runtime.h>
#include <cuda_fp16.h>
#include <cuda_bf16.h>

#define SEQ    3072
#define HID    1280
#define NHEAD  16
#define HD     80
#define SEGLEN 512
#define NSEG   6
#define QKVN   3840

// ---------------- scratch (no allocations allowed) ----------------
__device__ float  g_qkv[SEQ * QKVN];           // qkv fp32
__device__ __half g_q[NHEAD * SEQ * HD];       // [h][s][d]
__device__ __half g_k[NHEAD * SEQ * HD];
__device__ __half g_v[NHEAD * SEQ * HD];
__device__ float  g_attn[SEQ * HID];           // attention output (fp16-rounded values)

// bf16 hi/lo split scratch
__device__ __nv_bfloat16 g_hid_hi[SEQ * HID],   g_hid_lo[SEQ * HID];
__device__ __nv_bfloat16 g_wqkv_hi[QKVN * HID], g_wqkv_lo[QKVN * HID];
__device__ __nv_bfloat16 g_wpr_hi[HID * HID],   g_wpr_lo[HID * HID];
__device__ __nv_bfloat16 g_at_hi[SEQ * HID],    g_at_lo[SEQ * HID];

// ---------------- fp32 -> bf16 hi/lo split ----------------
__global__ __launch_bounds__(256) void split_kernel(
    const float* __restrict__ src,
    __nv_bfloat16* __restrict__ hi, __nv_bfloat16* __restrict__ lo, int n4)
{
    int i = blockIdx.x * blockDim.x + threadIdx.x;
    if (i >= n4) return;
    float4 x = ((const float4*)src)[i];
    __nv_bfloat16 h0 = __float2bfloat16(x.x);
    __nv_bfloat16 h1 = __float2bfloat16(x.y);
    __nv_bfloat16 h2 = __float2bfloat16(x.z);
    __nv_bfloat16 h3 = __float2bfloat16(x.w);
    __nv_bfloat16 l0 = __float2bfloat16(x.x - __bfloat162float(h0));
    __nv_bfloat16 l1 = __float2bfloat16(x.y - __bfloat162float(h1));
    __nv_bfloat16 l2 = __float2bfloat16(x.z - __bfloat162float(h2));
    __nv_bfloat16 l3 = __float2bfloat16(x.w - __bfloat162float(h3));
    ((__nv_bfloat162*)hi)[i * 2]     = __halves2bfloat162(h0, h1);
    ((__nv_bfloat162*)hi)[i * 2 + 1] = __halves2bfloat162(h2, h3);
    ((__nv_bfloat162*)lo)[i * 2]     = __halves2bfloat162(l0, l1);
    ((__nv_bfloat162*)lo)[i * 2 + 1] = __halves2bfloat162(l2, l3);
}

// ---------------- bf16x3 tensor-core GEMM ----------------
// C[M,N] = (Ah+Al)[M,K] * (Bh+Bl)[N,K]^T + bias[N]   (drop Al*Bl)
// BM=BN=128, BK=32, 256 threads (8 warps, 2x4), warp tile 64x32, m16n8k16.
#define SPAD 40   // smem row pitch (bf16) -> conflict-free ldmatrix

__device__ __forceinline__ void mma_bf16(
    float& c0, float& c1, float& c2, float& c3,
    unsigned a0, unsigned a1, unsigned a2, unsigned a3,
    unsigned b0, unsigned b1)
{
    asm volatile(
        "mma.sync.aligned.m16n8k16.row.col.f32.bf16.bf16.f32 "
        "{%0,%1,%2,%3}, {%4,%5,%6,%7}, {%8,%9}, {%0,%1,%2,%3};"
        : "+f"(c0), "+f"(c1), "+f"(c2), "+f"(c3)
        : "r"(a0), "r"(a1), "r"(a2), "r"(a3), "r"(b0), "r"(b1));
}

__device__ __forceinline__ void ldsm_x4(unsigned* r, const __nv_bfloat16* p)
{
    unsigned addr = (unsigned)__cvta_generic_to_shared(p);
    asm volatile("ldmatrix.sync.aligned.m8n8.x4.shared.b16 {%0,%1,%2,%3}, [%4];"
                 : "=r"(r[0]), "=r"(r[1]), "=r"(r[2]), "=r"(r[3]) : "r"(addr));
}

__device__ __forceinline__ void ldsm_x2(unsigned* r, const __nv_bfloat16* p)
{
    unsigned addr = (unsigned)__cvta_generic_to_shared(p);
    asm volatile("ldmatrix.sync.aligned.m8n8.x2.shared.b16 {%0,%1}, [%2];"
                 : "=r"(r[0]), "=r"(r[1]) : "r"(addr));
}

__global__ __launch_bounds__(256, 2) void bgemm3(
    const __nv_bfloat16* __restrict__ Ah, const __nv_bfloat16* __restrict__ Al,
    const __nv_bfloat16* __restrict__ Bh, const __nv_bfloat16* __restrict__ Bl,
    const float* __restrict__ bias, float* __restrict__ C,
    int M, int N, int K)
{
    __shared__ __nv_bfloat16 sAh[128 * SPAD], sAl[128 * SPAD];
    __shared__ __nv_bfloat16 sBh[128 * SPAD], sBl[128 * SPAD];

    const int t    = threadIdx.x;
    const int lane = t & 31;
    const int warp = t >> 5;
    const int mw   = warp >> 2;        // 0..1
    const int nw   = warp & 3;         // 0..3
    const int bm   = blockIdx.y * 128;
    const int bn   = blockIdx.x * 128;

    const int lrow = t >> 1;           // 0..127
    const int lko  = (t & 1) * 16;     // 0 or 16

    const size_t gA = (size_t)(bm + lrow) * K + lko;
    const size_t gB = (size_t)(bn + lrow) * K + lko;
    __nv_bfloat16* sAhp = &sAh[lrow * SPAD + lko];
    __nv_bfloat16* sAlp = &sAl[lrow * SPAD + lko];
    __nv_bfloat16* sBhp = &sBh[lrow * SPAD + lko];
    __nv_bfloat16* sBlp = &sBl[lrow * SPAD + lko];

    float acc[4][4][4];
#pragma unroll
    for (int i = 0; i < 4; i++)
#pragma unroll
        for (int j = 0; j < 4; j++)
#pragma unroll
            for (int e = 0; e < 4; e++) acc[i][j][e] = 0.0f;

    // ldmatrix source pointers (per-lane)
    const int a_row = (lane & 15);
    const int a_col = (lane >> 4) * 8;
    const int b_row = (lane & 7);
    const int b_col = ((lane >> 3) & 1) * 8;

    for (int k0 = 0; k0 < K; k0 += 32) {
        {
            uint4 vah0 = *(const uint4*)(Ah + gA + k0);
            uint4 vah1 = *(const uint4*)(Ah + gA + k0 + 8);
            uint4 val0 = *(const uint4*)(Al + gA + k0);
            uint4 val1 = *(const uint4*)(Al + gA + k0 + 8);
            uint4 vbh0 = *(const uint4*)(Bh + gB + k0);
            uint4 vbh1 = *(const uint4*)(Bh + gB + k0 + 8);
            uint4 vbl0 = *(const uint4*)(Bl + gB + k0);
            uint4 vbl1 = *(const uint4*)(Bl + gB + k0 + 8);
            *(uint4*)(sAhp)     = vah0;  *(uint4*)(sAhp + 8) = vah1;
            *(uint4*)(sAlp)     = val0;  *(uint4*)(sAlp + 8) = val1;
            *(uint4*)(sBhp)     = vbh0;  *(uint4*)(sBhp + 8) = vbh1;
            *(uint4*)(sBlp)     = vbl0;  *(uint4*)(sBlp + 8) = vbl1;
        }
        __syncthreads();

#pragma unroll
        for (int ks = 0; ks < 32; ks += 16) {
            unsigned bh[4][2], bl[4][2], af[4][4];
            // B fragments (hi & lo)
#pragma unroll
            for (int nt = 0; nt < 4; nt++) {
                const int br = nw * 32 + nt * 8 + b_row;
                ldsm_x2(bh[nt], &sBh[br * SPAD + ks + b_col]);
                ldsm_x2(bl[nt], &sBl[br * SPAD + ks + b_col]);
            }
            // A-hi fragments, then Ah*Bh and Ah*Bl
#pragma unroll
            for (int mt = 0; mt < 4; mt++) {
                const int ar = mw * 64 + mt * 16 + a_row;
                ldsm_x4(af[mt], &sAh[ar * SPAD + ks + a_col]);
            }
#pragma unroll
            for (int mt = 0; mt < 4; mt++)
#pragma unroll
                for (int nt = 0; nt < 4; nt++) {
                    mma_bf16(acc[mt][nt][0], acc[mt][nt][1], acc[mt][nt][2], acc[mt][nt][3],
                             af[mt][0], af[mt][1], af[mt][2], af[mt][3],
                             bh[nt][0], bh[nt][1]);
                    mma_bf16(acc[mt][nt][0], acc[mt][nt][1], acc[mt][nt][2], acc[mt][nt][3],
                             af[mt][0], af[mt][1], af[mt][2], af[mt][3],
                             bl[nt][0], bl[nt][1]);
                }
            // A-lo fragments, Al*Bh
#pragma unroll
            for (int mt = 0; mt < 4; mt++) {
                const int ar = mw * 64 + mt * 16 + a_row;
                ldsm_x4(af[mt], &sAl[ar * SPAD + ks + a_col]);
            }
#pragma unroll
            for (int mt = 0; mt < 4; mt++)
#pragma unroll
                for (int nt = 0; nt < 4; nt++)
                    mma_bf16(acc[mt][nt][0], acc[mt][nt][1], acc[mt][nt][2], acc[mt][nt][3],
                             af[mt][0], af[mt][1], af[mt][2], af[mt][3],
                             bh[nt][0], bh[nt][1]);
        }
        __syncthreads();
    }

    // epilogue: add bias, store
#pragma unroll
    for (int mt = 0; mt < 4; mt++) {
        const int r0 = bm + mw * 64 + mt * 16 + (lane >> 2);
        const int r1 = r0 + 8;
#pragma unroll
        for (int nt = 0; nt < 4; nt++) {
            const int c = bn + nw * 32 + nt * 8 + (lane & 3) * 2;
            const float bv0 = bias[c], bv1 = bias[c + 1];
            float2 o0 = {acc[mt][nt][0] + bv0, acc[mt][nt][1] + bv1};
            float2 o1 = {acc[mt][nt][2] + bv0, acc[mt][nt][3] + bv1};
            *(float2*)&C[(size_t)r0 * N + c] = o0;
            *(float2*)&C[(size_t)r1 * N + c] = o1;
        }
    }
}

// ---------------- RoPE + fp16 cast ----------------
__global__ __launch_bounds__(256) void rope_cast_kernel(
    const float* __restrict__ qkv,
    const float* __restrict__ cosp, const float* __restrict__ sinp,
    __half* __restrict__ q, __half* __restrict__ k, __half* __restrict__ v)
{
    int idx = blockIdx.x * blockDim.x + threadIdx.x;   // SEQ*NHEAD*40
    if (idx >= SEQ * NHEAD * 40) return;
    int d = idx % 40;
    int h = (idx / 40) % NHEAD;
    int s = idx / (40 * NHEAD);

    float c  = cosp[s * HD + d];
    float sn = sinp[s * HD + d];

    int base = s * QKVN + h * HD + d;
    float q1 = qkv[base],            q2 = qkv[base + 40];
    float k1 = qkv[base + HID],      k2 = qkv[base + HID + 40];
    float v1 = qkv[base + 2 * HID],  v2 = qkv[base + 2 * HID + 40];

    int o = (h * SEQ + s) * HD + d;
    q[o]      = __float2half(q1 * c - q2 * sn);
    q[o + 40] = __float2half(q2 * c + q1 * sn);
    k[o]      = __float2half(k1 * c - k2 * sn);
    k[o + 40] = __float2half(k2 * c + k1 * sn);
    v[o]      = __float2half(v1);
    v[o + 40] = __float2half(v2);
}

// ---------------- attention (unchanged, known-correct) ----------------
#define ATTN_SMEM (80 * 128 * 4 + 80 * 128 * 4 + 128 * 512 * 2 + 256 * 4)

__global__ __launch_bounds__(256) void attn_kernel(
    const __half* __restrict__ q, const __half* __restrict__ k,
    const __half* __restrict__ v, float* __restrict__ attn_out)
{
    extern __shared__ char smraw[];
    float*  Qs   = (float*)smraw;
    float*  KVs  = Qs + 80 * 128;
    __half* Ss   = (__half*)(KVs + 80 * 128);
    float*  mrow = (float*)(Ss + 128 * 512);
    float*  lrow = mrow + 128;

    const int tid  = threadIdx.x;
    const int tx   = tid & 15;
    const int ty   = tid >> 4;
    const int h    = blockIdx.y;
    const int seg  = blockIdx.x >> 2;
    const int qc   = blockIdx.x & 3;
    const int qbase = seg * SEGLEN + qc * 128;
    const int kbase = seg * SEGLEN;
    const float scale = 0.11180339887498949f;

    for (int i = tid; i < 128 * HD; i += 256) {
        int r = i / HD, d = i % HD;
        Qs[d * 128 + r] = __half2float(q[(size_t)(h * SEQ + qbase + r) * HD + d]);
    }

    for (int kt = 0; kt < 4; kt++) {
        __syncthreads();
        for (int i = tid; i < 128 * HD; i += 256) {
            int r = i / HD, d = i % HD;
            KVs[d * 128 + r] =
                __half2float(k[(size_t)(h * SEQ + kbase + kt * 128 + r) * HD + d]);
        }
        __syncthreads();

        float acc[8][8];
#pragma unroll
        for (int i = 0; i < 8; i++)
#pragma unroll
            for (int j = 0; j < 8; j++) acc[i][j] = 0.0f;

        for (int d = 0; d < HD; d++) {
            float4 a0 = *(const float4*)&Qs[d * 128 + ty * 8];
            float4 a1 = *(const float4*)&Qs[d * 128 + ty * 8 + 4];
            float4 b0 = *(const float4*)&KVs[d * 128 + tx * 8];
            float4 b1 = *(const float4*)&KVs[d * 128 + tx * 8 + 4];
            float ar[8] = {a0.x, a0.y, a0.z, a0.w, a1.x, a1.y, a1.z, a1.w};
            float br[8] = {b0.x, b0.y, b0.z, b0.w, b1.x, b1.y, b1.z, b1.w};
#pragma unroll
            for (int i = 0; i < 8; i++)
#pragma unroll
                for (int j = 0; j < 8; j++)
                    acc[i][j] = fmaf(ar[i], br[j], acc[i][j]);
        }

#pragma unroll
        for (int i = 0; i < 8; i++) {
            __half hs[8];
#pragma unroll
            for (int j = 0; j < 8; j++) hs[j] = __float2half(acc[i][j] * scale);
            *(uint4*)&Ss[(ty * 8 + i) * 512 + kt * 128 + tx * 8] = *(uint4*)hs;
        }
    }
    __syncthreads();

    {
        const int warp = tid >> 5, lane = tid & 31;
        for (int rr = 0; rr < 16; rr++) {
            int r = warp * 16 + rr;
            float m = -1e30f;
            for (int c = lane; c < 512; c += 32)
                m = fmaxf(m, __half2float(Ss[r * 512 + c]));
#pragma unroll
            for (int o = 16; o; o >>= 1)
                m = fmaxf(m, __shfl_xor_sync(0xffffffffu, m, o));
            float l = 0.0f;
            for (int c = lane; c < 512; c += 32)
                l += expf(__half2float(Ss[r * 512 + c]) - m);
#pragma unroll
            for (int o = 16; o; o >>= 1)
                l += __shfl_xor_sync(0xffffffffu, l, o);
            if (lane == 0) { mrow[r] = m; lrow[r] = l; }
        }
    }
    __syncthreads();

    for (int i = tid; i < 128 * 512; i += 256) {
        int r = i >> 9;
        float w = expf(__half2float(Ss[i]) - mrow[r]) / lrow[r];
        Ss[i] = __float2half(w);
    }

    float oacc[8][5];
#pragma unroll
    for (int i = 0; i < 8; i++)
#pragma unroll
        for (int j = 0; j < 5; j++) oacc[i][j] = 0.0f;

    for (int kt = 0; kt < 4; kt++) {
        __syncthreads();
        for (int i = tid; i < 128 * HD; i += 256) {
            int r = i / HD, d = i % HD;
            KVs[r * HD + d] =
                __half2float(v[(size_t)(h * SEQ + kbase + kt * 128 + r) * HD + d]);
        }
        __syncthreads();

        for (int kk = 0; kk < 128; kk++) {
            float w[8];
#pragma unroll
            for (int i = 0; i < 8; i++)
                w[i] = __half2float(Ss[(ty * 8 + i) * 512 + kt * 128 + kk]);
#pragma unroll
            for (int j = 0; j < 5; j++) {
                float vv = KVs[kk * HD + tx * 5 + j];
#pragma unroll
                for (int i = 0; i < 8; i++)
                    oacc[i][j] = fmaf(w[i], vv, oacc[i][j]);
            }
        }
    }

#pragma unroll
    for (int i = 0; i < 8; i++) {
        int row = qbase + ty * 8 + i;
#pragma unroll
        for (int j = 0; j < 5; j++) {
            float val = __half2float(__float2half(oacc[i][j]));
            attn_out[(size_t)row * HID + h * HD + tx * 5 + j] = val;
        }
    }
}

// ---------------- launch ----------------
extern "C" void kernel_launch(void* const* d_in, const int* in_sizes, int n_in,
                              void* d_out, int out_size)
{
    const float* hidden = (const float*)d_in[0];
    const float* cosp   = (const float*)d_in[1];
    const float* sinp   = (const float*)d_in[2];
    const float* w_qkv  = (const float*)d_in[3];
    const float* b_qkv  = (const float*)d_in[4];
    const float* w_proj = (const float*)d_in[5];
    const float* b_proj = (const float*)d_in[6];
    float* out = (float*)d_out;

    float *qkv_p, *attn_p;
    __half *q_p, *k_p, *v_p;
    __nv_bfloat16 *hid_hi, *hid_lo, *wqkv_hi, *wqkv_lo, *wpr_hi, *wpr_lo, *at_hi, *at_lo;
    cudaGetSymbolAddress((void**)&qkv_p, g_qkv);
    cudaGetSymbolAddress((void**)&q_p, g_q);
    cudaGetSymbolAddress((void**)&k_p, g_k);
    cudaGetSymbolAddress((void**)&v_p, g_v);
    cudaGetSymbolAddress((void**)&attn_p, g_attn);
    cudaGetSymbolAddress((void**)&hid_hi, g_hid_hi);
    cudaGetSymbolAddress((void**)&hid_lo, g_hid_lo);
    cudaGetSymbolAddress((void**)&wqkv_hi, g_wqkv_hi);
    cudaGetSymbolAddress((void**)&wqkv_lo, g_wqkv_lo);
    cudaGetSymbolAddress((void**)&wpr_hi, g_wpr_hi);
    cudaGetSymbolAddress((void**)&wpr_lo, g_wpr_lo);
    cudaGetSymbolAddress((void**)&at_hi, g_at_hi);
    cudaGetSymbolAddress((void**)&at_lo, g_at_lo);

    cudaFuncSetAttribute(attn_kernel,
                         cudaFuncAttributeMaxDynamicSharedMemorySize, ATTN_SMEM);

    // 0) bf16 hi/lo splits of hidden and w_qkv
    split_kernel<<<(SEQ * HID / 4 + 255) / 256, 256>>>(hidden, hid_hi, hid_lo, SEQ * HID / 4);
    split_kernel<<<(QKVN * HID / 4 + 255) / 256, 256>>>(w_qkv, wqkv_hi, wqkv_lo, QKVN * HID / 4);

    // 1) QKV GEMM on tensor cores
    bgemm3<<<dim3(QKVN / 128, SEQ / 128), 256>>>(
        hid_hi, hid_lo, wqkv_hi, wqkv_lo, b_qkv, qkv_p, SEQ, QKVN, HID);

    // 2) RoPE + fp16 cast
    rope_cast_kernel<<<(SEQ * NHEAD * 40) / 256, 256>>>(
        qkv_p, cosp, sinp, q_p, k_p, v_p);

    // 3) block-diagonal attention
    attn_kernel<<<dim3(NSEG * 4, NHEAD), 256, ATTN_SMEM>>>(
        q_p, k_p, v_p, attn_p);

    // 4) split attn output + w_proj, then proj GEMM on tensor cores
    split_kernel<<<(SEQ * HID / 4 + 255) / 256, 256>>>(attn_p, at_hi, at_lo, SEQ * HID / 4);
    split_kernel<<<(HID * HID / 4 + 255) / 256, 256>>>(w_proj, wpr_hi, wpr_lo, HID * HID / 4);

    bgemm3<<<dim3(HID / 128, SEQ / 128), 256>>>(
        at_hi, at_lo, wpr_hi, wpr_lo, b_proj, out, SEQ, HID, HID);
}

// round 3
// speedup vs baseline: 2.5032x; 1.4206x over previous
#include <cuda_runtime.h>
#include <cuda_fp16.h>
#include <cuda_bf16.h>

#define SEQ    3072
#define HID    1280
#define NHEAD  16
#define HD     80
#define SEGLEN 512
#define NSEG   6
#define QKVN   3840

// ---------------- scratch (no allocations allowed) ----------------
__device__ float  g_qkv[SEQ * QKVN];
__device__ __half g_q[NHEAD * SEQ * HD];       // [h][s][d]
__device__ __half g_k[NHEAD * SEQ * HD];
__device__ __half g_v[NHEAD * SEQ * HD];
__device__ float  g_attn[SEQ * HID];

__device__ __nv_bfloat16 g_hid_hi[SEQ * HID],   g_hid_lo[SEQ * HID];
__device__ __nv_bfloat16 g_wqkv_hi[QKVN * HID], g_wqkv_lo[QKVN * HID];
__device__ __nv_bfloat16 g_wpr_hi[HID * HID],   g_wpr_lo[HID * HID];
__device__ __nv_bfloat16 g_at_hi[SEQ * HID],    g_at_lo[SEQ * HID];

// ---------------- helpers ----------------
__device__ __forceinline__ void cp16(void* dst, const void* src)
{
    unsigned d = (unsigned)__cvta_generic_to_shared(dst);
    asm volatile("cp.async.cg.shared.global [%0], [%1], 16;" :: "r"(d), "l"(src));
}

__device__ __forceinline__ void mma_bf16(
    float& c0, float& c1, float& c2, float& c3,
    unsigned a0, unsigned a1, unsigned a2, unsigned a3,
    unsigned b0, unsigned b1)
{
    asm volatile(
        "mma.sync.aligned.m16n8k16.row.col.f32.bf16.bf16.f32 "
        "{%0,%1,%2,%3}, {%4,%5,%6,%7}, {%8,%9}, {%0,%1,%2,%3};"
        : "+f"(c0), "+f"(c1), "+f"(c2), "+f"(c3)
        : "r"(a0), "r"(a1), "r"(a2), "r"(a3), "r"(b0), "r"(b1));
}

__device__ __forceinline__ void mma_f16(
    float& c0, float& c1, float& c2, float& c3,
    unsigned a0, unsigned a1, unsigned a2, unsigned a3,
    unsigned b0, unsigned b1)
{
    asm volatile(
        "mma.sync.aligned.m16n8k16.row.col.f32.f16.f16.f32 "
        "{%0,%1,%2,%3}, {%4,%5,%6,%7}, {%8,%9}, {%0,%1,%2,%3};"
        : "+f"(c0), "+f"(c1), "+f"(c2), "+f"(c3)
        : "r"(a0), "r"(a1), "r"(a2), "r"(a3), "r"(b0), "r"(b1));
}

__device__ __forceinline__ void ldsm_x4(unsigned* r, const void* p)
{
    unsigned addr = (unsigned)__cvta_generic_to_shared(p);
    asm volatile("ldmatrix.sync.aligned.m8n8.x4.shared.b16 {%0,%1,%2,%3}, [%4];"
                 : "=r"(r[0]), "=r"(r[1]), "=r"(r[2]), "=r"(r[3]) : "r"(addr));
}
__device__ __forceinline__ void ldsm_x2(unsigned* r, const void* p)
{
    unsigned addr = (unsigned)__cvta_generic_to_shared(p);
    asm volatile("ldmatrix.sync.aligned.m8n8.x2.shared.b16 {%0,%1}, [%2];"
                 : "=r"(r[0]), "=r"(r[1]) : "r"(addr));
}
__device__ __forceinline__ void ldsm_x2t(unsigned* r, const void* p)
{
    unsigned addr = (unsigned)__cvta_generic_to_shared(p);
    asm volatile("ldmatrix.sync.aligned.m8n8.x2.trans.shared.b16 {%0,%1}, [%2];"
                 : "=r"(r[0]), "=r"(r[1]) : "r"(addr));
}

// ---------------- fp32 -> bf16 hi/lo split ----------------
__global__ __launch_bounds__(256) void split_kernel(
    const float* __restrict__ src,
    __nv_bfloat16* __restrict__ hi, __nv_bfloat16* __restrict__ lo, int n4)
{
    int i = blockIdx.x * blockDim.x + threadIdx.x;
    if (i >= n4) return;
    float4 x = ((const float4*)src)[i];
    __nv_bfloat16 h0 = __float2bfloat16(x.x);
    __nv_bfloat16 h1 = __float2bfloat16(x.y);
    __nv_bfloat16 h2 = __float2bfloat16(x.z);
    __nv_bfloat16 h3 = __float2bfloat16(x.w);
    __nv_bfloat16 l0 = __float2bfloat16(x.x - __bfloat162float(h0));
    __nv_bfloat16 l1 = __float2bfloat16(x.y - __bfloat162float(h1));
    __nv_bfloat16 l2 = __float2bfloat16(x.z - __bfloat162float(h2));
    __nv_bfloat16 l3 = __float2bfloat16(x.w - __bfloat162float(h3));
    ((__nv_bfloat162*)hi)[i * 2]     = __halves2bfloat162(h0, h1);
    ((__nv_bfloat162*)hi)[i * 2 + 1] = __halves2bfloat162(h2, h3);
    ((__nv_bfloat162*)lo)[i * 2]     = __halves2bfloat162(l0, l1);
    ((__nv_bfloat162*)lo)[i * 2 + 1] = __halves2bfloat162(l2, l3);
}

// ---------------- bf16x3 tensor-core GEMM, cp.async double-buffered ----------------
#define SPAD 40
#define GSTG (128 * SPAD)          // halves per array per stage
#define GEMM_SMEM (8 * GSTG * 2)   // bytes: 4 arrays x 2 stages x 2B

__global__ __launch_bounds__(256, 2) void bgemm3(
    const __nv_bfloat16* __restrict__ Ah, const __nv_bfloat16* __restrict__ Al,
    const __nv_bfloat16* __restrict__ Bh, const __nv_bfloat16* __restrict__ Bl,
    const float* __restrict__ bias, float* __restrict__ C,
    int M, int N, int K)
{
    extern __shared__ __nv_bfloat16 smg[];
    __nv_bfloat16* sAh = smg;
    __nv_bfloat16* sAl = smg + 2 * GSTG;
    __nv_bfloat16* sBh = smg + 4 * GSTG;
    __nv_bfloat16* sBl = smg + 6 * GSTG;

    const int t    = threadIdx.x;
    const int lane = t & 31;
    const int warp = t >> 5;
    const int mw   = warp >> 2;
    const int nw   = warp & 3;
    const int bm   = blockIdx.y * 128;
    const int bn   = blockIdx.x * 128;

    const int lrow = t >> 1;
    const int lko  = (t & 1) * 16;
    const int soff = lrow * SPAD + lko;

    const size_t gA = (size_t)(bm + lrow) * K + lko;
    const size_t gB = (size_t)(bn + lrow) * K + lko;

    float acc[4][4][4];
#pragma unroll
    for (int i = 0; i < 4; i++)
#pragma unroll
        for (int j = 0; j < 4; j++)
#pragma unroll
            for (int e = 0; e < 4; e++) acc[i][j][e] = 0.0f;

    const int a_row = (lane & 15);
    const int a_col = (lane >> 4) * 8;
    const int b_row = (lane & 7);
    const int b_col = ((lane >> 3) & 1) * 8;

#define PREFETCH(k0, s) do {                                            \
        int st = (s) * GSTG;                                            \
        cp16(sAh + st + soff,     Ah + gA + (k0));                      \
        cp16(sAh + st + soff + 8, Ah + gA + (k0) + 8);                  \
        cp16(sAl + st + soff,     Al + gA + (k0));                      \
        cp16(sAl + st + soff + 8, Al + gA + (k0) + 8);                  \
        cp16(sBh + st + soff,     Bh + gB + (k0));                      \
        cp16(sBh + st + soff + 8, Bh + gB + (k0) + 8);                  \
        cp16(sBl + st + soff,     Bl + gB + (k0));                      \
        cp16(sBl + st + soff + 8, Bl + gB + (k0) + 8);                  \
    } while (0)

    PREFETCH(0, 0);
    asm volatile("cp.async.commit_group;");

    int s = 0;
    for (int k0 = 0; k0 < K; k0 += 32, s ^= 1) {
        if (k0 + 32 < K) {
            PREFETCH(k0 + 32, s ^ 1);
            asm volatile("cp.async.commit_group;");
            asm volatile("cp.async.wait_group 1;");
        } else {
            asm volatile("cp.async.wait_group 0;");
        }
        __syncthreads();

        const int st = s * GSTG;
#pragma unroll
        for (int ks = 0; ks < 32; ks += 16) {
            unsigned bh[4][2], bl[4][2], af[4][4];
#pragma unroll
            for (int nt = 0; nt < 4; nt++) {
                const int br = nw * 32 + nt * 8 + b_row;
                ldsm_x2(bh[nt], &sBh[st + br * SPAD + ks + b_col]);
                ldsm_x2(bl[nt], &sBl[st + br * SPAD + ks + b_col]);
            }
#pragma unroll
            for (int mt = 0; mt < 4; mt++) {
                const int ar = mw * 64 + mt * 16 + a_row;
                ldsm_x4(af[mt], &sAh[st + ar * SPAD + ks + a_col]);
            }
#pragma unroll
            for (int mt = 0; mt < 4; mt++)
#pragma unroll
                for (int nt = 0; nt < 4; nt++) {
                    mma_bf16(acc[mt][nt][0], acc[mt][nt][1], acc[mt][nt][2], acc[mt][nt][3],
                             af[mt][0], af[mt][1], af[mt][2], af[mt][3],
                             bh[nt][0], bh[nt][1]);
                    mma_bf16(acc[mt][nt][0], acc[mt][nt][1], acc[mt][nt][2], acc[mt][nt][3],
                             af[mt][0], af[mt][1], af[mt][2], af[mt][3],
                             bl[nt][0], bl[nt][1]);
                }
#pragma unroll
            for (int mt = 0; mt < 4; mt++) {
                const int ar = mw * 64 + mt * 16 + a_row;
                ldsm_x4(af[mt], &sAl[st + ar * SPAD + ks + a_col]);
            }
#pragma unroll
            for (int mt = 0; mt < 4; mt++)
#pragma unroll
                for (int nt = 0; nt < 4; nt++)
                    mma_bf16(acc[mt][nt][0], acc[mt][nt][1], acc[mt][nt][2], acc[mt][nt][3],
                             af[mt][0], af[mt][1], af[mt][2], af[mt][3],
                             bh[nt][0], bh[nt][1]);
        }
        __syncthreads();
    }

#pragma unroll
    for (int mt = 0; mt < 4; mt++) {
        const int r0 = bm + mw * 64 + mt * 16 + (lane >> 2);
        const int r1 = r0 + 8;
#pragma unroll
        for (int nt = 0; nt < 4; nt++) {
            const int c = bn + nw * 32 + nt * 8 + (lane & 3) * 2;
            const float bv0 = bias[c], bv1 = bias[c + 1];
            float2 o0 = {acc[mt][nt][0] + bv0, acc[mt][nt][1] + bv1};
            float2 o1 = {acc[mt][nt][2] + bv0, acc[mt][nt][3] + bv1};
            *(float2*)&C[(size_t)r0 * N + c] = o0;
            *(float2*)&C[(size_t)r1 * N + c] = o1;
        }
    }
}

// ---------------- RoPE + fp16 cast ----------------
__global__ __launch_bounds__(256) void rope_cast_kernel(
    const float* __restrict__ qkv,
    const float* __restrict__ cosp, const float* __restrict__ sinp,
    __half* __restrict__ q, __half* __restrict__ k, __half* __restrict__ v)
{
    int idx = blockIdx.x * blockDim.x + threadIdx.x;
    if (idx >= SEQ * NHEAD * 40) return;
    int d = idx % 40;
    int h = (idx / 40) % NHEAD;
    int s = idx / (40 * NHEAD);

    float c  = cosp[s * HD + d];
    float sn = sinp[s * HD + d];

    int base = s * QKVN + h * HD + d;
    float q1 = qkv[base],            q2 = qkv[base + 40];
    float k1 = qkv[base + HID],      k2 = qkv[base + HID + 40];
    float v1 = qkv[base + 2 * HID],  v2 = qkv[base + 2 * HID + 40];

    int o = (h * SEQ + s) * HD + d;
    q[o]      = __float2half(q1 * c - q2 * sn);
    q[o + 40] = __float2half(q2 * c + q1 * sn);
    k[o]      = __float2half(k1 * c - k2 * sn);
    k[o + 40] = __float2half(k2 * c + k1 * sn);
    v[o]      = __float2half(v1);
    v[o + 40] = __float2half(v2);
}

// ---------------- attention: fp16 tensor-core MMA ----------------
// Block = (head, segment, 128-query chunk). 8 warps; warp owns 16 query rows.
#define QPITCH 88
#define SPITCH 520
#define ATTN_SMEM ((128 * QPITCH + 128 * QPITCH + 128 * SPITCH) * 2 + 2 * 128 * 4)

__global__ __launch_bounds__(256) void attn_kernel(
    const __half* __restrict__ q, const __half* __restrict__ k,
    const __half* __restrict__ v, float* __restrict__ attn_out)
{
    extern __shared__ char smraw[];
    __half* sQ   = (__half*)smraw;                     // [128][QPITCH]
    __half* sKV  = sQ + 128 * QPITCH;                  // [128][QPITCH]
    __half* Ss   = sKV + 128 * QPITCH;                 // [128][SPITCH]
    float*  mrow = (float*)(Ss + 128 * SPITCH);        // [128]
    float*  lrow = mrow + 128;

    const int tid  = threadIdx.x;
    const int lane = tid & 31;
    const int w    = tid >> 5;                         // warp 0..7
    const int h    = blockIdx.y;
    const int seg  = blockIdx.x >> 2;
    const int qc   = blockIdx.x & 3;
    const int qbase = seg * SEGLEN + qc * 128;
    const int kbase = seg * SEGLEN;
    const float scale = 0.11180339887498949f;          // 80^-0.5

    const int a_row = (lane & 15);
    const int a_col = (lane >> 4) * 8;
    const int b_row = (lane & 7);
    const int b_col = ((lane >> 3) & 1) * 8;

    // load Q chunk: [128][80] fp16, row-major, pitch 88
    for (int i = tid; i < 128 * 10; i += 256) {
        int r = i / 10, c8 = (i % 10) * 8;
        *(uint4*)&sQ[r * QPITCH + c8] =
            *(const uint4*)&q[(size_t)(h * SEQ + qbase + r) * HD + c8];
    }

    // ---- pass 1: scores = scale * Q K^T -> Ss fp16 ----
    for (int kt = 0; kt < 4; kt++) {
        __syncthreads();
        for (int i = tid; i < 128 * 10; i += 256) {
            int r = i / 10, c8 = (i % 10) * 8;
            *(uint4*)&sKV[r * QPITCH + c8] =
                *(const uint4*)&k[(size_t)(h * SEQ + kbase + kt * 128 + r) * HD + c8];
        }
        __syncthreads();

        float acc[16][4];
#pragma unroll
        for (int nt = 0; nt < 16; nt++)
#pragma unroll
            for (int e = 0; e < 4; e++) acc[nt][e] = 0.0f;

#pragma unroll
        for (int ks = 0; ks < 80; ks += 16) {
            unsigned af[4];
            ldsm_x4(af, &sQ[(w * 16 + a_row) * QPITCH + ks + a_col]);
#pragma unroll
            for (int nt = 0; nt < 16; nt++) {
                unsigned bf[2];
                ldsm_x2(bf, &sKV[(nt * 8 + b_row) * QPITCH + ks + b_col]);
                mma_f16(acc[nt][0], acc[nt][1], acc[nt][2], acc[nt][3],
                        af[0], af[1], af[2], af[3], bf[0], bf[1]);
            }
        }

        const int r0 = w * 16 + (lane >> 2);
#pragma unroll
        for (int nt = 0; nt < 16; nt++) {
            const int c = kt * 128 + nt * 8 + (lane & 3) * 2;
            *(__half2*)&Ss[r0 * SPITCH + c] =
                __floats2half2_rn(acc[nt][0] * scale, acc[nt][1] * scale);
            *(__half2*)&Ss[(r0 + 8) * SPITCH + c] =
                __floats2half2_rn(acc[nt][2] * scale, acc[nt][3] * scale);
        }
    }
    __syncthreads();

    // ---- softmax stats: each warp handles its 16 rows ----
    for (int rr = 0; rr < 16; rr++) {
        int r = w * 16 + rr;
        float m = -1e30f;
        for (int c = lane; c < 512; c += 32)
            m = fmaxf(m, __half2float(Ss[r * SPITCH + c]));
#pragma unroll
        for (int o = 16; o; o >>= 1)
            m = fmaxf(m, __shfl_xor_sync(0xffffffffu, m, o));
        float l = 0.0f;
        for (int c = lane; c < 512; c += 32)
            l += expf(__half2float(Ss[r * SPITCH + c]) - m);
#pragma unroll
        for (int o = 16; o; o >>= 1)
            l += __shfl_xor_sync(0xffffffffu, l, o);
        if (lane == 0) { mrow[r] = m; lrow[r] = l; }
    }
    __syncthreads();

    // ---- weights fp16 in place ----
    for (int i = tid; i < 128 * 512; i += 256) {
        int r = i >> 9, c = i & 511;
        float wgt = expf(__half2float(Ss[r * SPITCH + c]) - mrow[r]) / lrow[r];
        Ss[r * SPITCH + c] = __float2half(wgt);
    }

    // ---- pass 2: O = W @ V ----
    float oacc[10][4];
#pragma unroll
    for (int nt = 0; nt < 10; nt++)
#pragma unroll
        for (int e = 0; e < 4; e++) oacc[nt][e] = 0.0f;

    for (int kt = 0; kt < 4; kt++) {
        __syncthreads();   // covers weight conversion on kt==0, sKV reuse otherwise
        for (int i = tid; i < 128 * 10; i += 256) {
            int r = i / 10, c8 = (i % 10) * 8;
            *(uint4*)&sKV[r * QPITCH + c8] =
                *(const uint4*)&v[(size_t)(h * SEQ + kbase + kt * 128 + r) * HD + c8];
        }
        __syncthreads();

#pragma unroll
        for (int ks = 0; ks < 8; ks++) {
            unsigned af[4];
            ldsm_x4(af, &Ss[(w * 16 + a_row) * SPITCH + kt * 128 + ks * 16 + a_col]);
#pragma unroll
            for (int nt = 0; nt < 10; nt++) {
                unsigned bf[2];
                ldsm_x2t(bf, &sKV[(ks * 16 + (lane & 15)) * QPITCH + nt * 8]);
                mma_f16(oacc[nt][0], oacc[nt][1], oacc[nt][2], oacc[nt][3],
                        af[0], af[1], af[2], af[3], bf[0], bf[1]);
            }
        }
    }

    // write out, rounded through fp16 (reference attn output is fp16)
    const int r0 = qbase + w * 16 + (lane >> 2);
#pragma unroll
    for (int nt = 0; nt < 10; nt++) {
        const int c = h * HD + nt * 8 + (lane & 3) * 2;
        float2 o0 = {__half2float(__float2half(oacc[nt][0])),
                     __half2float(__float2half(oacc[nt][1]))};
        float2 o1 = {__half2float(__float2half(oacc[nt][2])),
                     __half2float(__float2half(oacc[nt][3]))};
        *(float2*)&attn_out[(size_t)r0 * HID + c] = o0;
        *(float2*)&attn_out[(size_t)(r0 + 8) * HID + c] = o1;
    }
}

// ---------------- launch ----------------
extern "C" void kernel_launch(void* const* d_in, const int* in_sizes, int n_in,
                              void* d_out, int out_size)
{
    const float* hidden = (const float*)d_in[0];
    const float* cosp   = (const float*)d_in[1];
    const float* sinp   = (const float*)d_in[2];
    const float* w_qkv  = (const float*)d_in[3];
    const float* b_qkv  = (const float*)d_in[4];
    const float* w_proj = (const float*)d_in[5];
    const float* b_proj = (const float*)d_in[6];
    float* out = (float*)d_out;

    float *qkv_p, *attn_p;
    __half *q_p, *k_p, *v_p;
    __nv_bfloat16 *hid_hi, *hid_lo, *wqkv_hi, *wqkv_lo, *wpr_hi, *wpr_lo, *at_hi, *at_lo;
    cudaGetSymbolAddress((void**)&qkv_p, g_qkv);
    cudaGetSymbolAddress((void**)&q_p, g_q);
    cudaGetSymbolAddress((void**)&k_p, g_k);
    cudaGetSymbolAddress((void**)&v_p, g_v);
    cudaGetSymbolAddress((void**)&attn_p, g_attn);
    cudaGetSymbolAddress((void**)&hid_hi, g_hid_hi);
    cudaGetSymbolAddress((void**)&hid_lo, g_hid_lo);
    cudaGetSymbolAddress((void**)&wqkv_hi, g_wqkv_hi);
    cudaGetSymbolAddress((void**)&wqkv_lo, g_wqkv_lo);
    cudaGetSymbolAddress((void**)&wpr_hi, g_wpr_hi);
    cudaGetSymbolAddress((void**)&wpr_lo, g_wpr_lo);
    cudaGetSymbolAddress((void**)&at_hi, g_at_hi);
    cudaGetSymbolAddress((void**)&at_lo, g_at_lo);

    cudaFuncSetAttribute(attn_kernel,
                         cudaFuncAttributeMaxDynamicSharedMemorySize, ATTN_SMEM);
    cudaFuncSetAttribute(bgemm3,
                         cudaFuncAttributeMaxDynamicSharedMemorySize, GEMM_SMEM);

    // 0) bf16 hi/lo splits
    split_kernel<<<(SEQ * HID / 4 + 255) / 256, 256>>>(hidden, hid_hi, hid_lo, SEQ * HID / 4);
    split_kernel<<<(QKVN * HID / 4 + 255) / 256, 256>>>(w_qkv, wqkv_hi, wqkv_lo, QKVN * HID / 4);

    // 1) QKV GEMM
    bgemm3<<<dim3(QKVN / 128, SEQ / 128), 256, GEMM_SMEM>>>(
        hid_hi, hid_lo, wqkv_hi, wqkv_lo, b_qkv, qkv_p, SEQ, QKVN, HID);

    // 2) RoPE + fp16 cast
    rope_cast_kernel<<<(SEQ * NHEAD * 40) / 256, 256>>>(
        qkv_p, cosp, sinp, q_p, k_p, v_p);

    // 3) block-diagonal attention (tensor cores)
    attn_kernel<<<dim3(NSEG * 4, NHEAD), 256, ATTN_SMEM>>>(
        q_p, k_p, v_p, attn_p);

    // 4) proj GEMM
    split_kernel<<<(SEQ * HID / 4 + 255) / 256, 256>>>(attn_p, at_hi, at_lo, SEQ * HID / 4);
    split_kernel<<<(HID * HID / 4 + 255) / 256, 256>>>(w_proj, wpr_hi, wpr_lo, HID * HID / 4);

    bgemm3<<<dim3(HID / 128, SEQ / 128), 256, GEMM_SMEM>>>(
        at_hi, at_lo, wpr_hi, wpr_lo, b_proj, out, SEQ, HID, HID);
}

// round 4
// speedup vs baseline: 3.1872x; 1.2732x over previous
#include <cuda_runtime.h>
#include <cuda_fp16.h>

#define SEQ    3072
#define HID    1280
#define NHEAD  16
#define HD     80
#define SEGLEN 512
#define NSEG   6
#define QKVN   3840

// ---------------- scratch (no allocations allowed) ----------------
__device__ float  g_qkv[SEQ * QKVN];
__device__ __half g_q[NHEAD * SEQ * HD];       // [h][s][d]
__device__ __half g_k[NHEAD * SEQ * HD];
__device__ __half g_v[NHEAD * SEQ * HD];
__device__ __half g_attn16[SEQ * HID];         // attention output, exact fp16

__device__ __half g_a16[SEQ * HID];            // hidden cast to fp16
__device__ __half g_wqkv_hi[QKVN * HID], g_wqkv_lo[QKVN * HID];
__device__ __half g_wpr_hi[HID * HID],   g_wpr_lo[HID * HID];

// ---------------- helpers ----------------
__device__ __forceinline__ void cp16(void* dst, const void* src)
{
    unsigned d = (unsigned)__cvta_generic_to_shared(dst);
    asm volatile("cp.async.cg.shared.global [%0], [%1], 16;" :: "r"(d), "l"(src));
}

__device__ __forceinline__ void mma_f16(
    float& c0, float& c1, float& c2, float& c3,
    unsigned a0, unsigned a1, unsigned a2, unsigned a3,
    unsigned b0, unsigned b1)
{
    asm volatile(
        "mma.sync.aligned.m16n8k16.row.col.f32.f16.f16.f32 "
        "{%0,%1,%2,%3}, {%4,%5,%6,%7}, {%8,%9}, {%0,%1,%2,%3};"
        : "+f"(c0), "+f"(c1), "+f"(c2), "+f"(c3)
        : "r"(a0), "r"(a1), "r"(a2), "r"(a3), "r"(b0), "r"(b1));
}

__device__ __forceinline__ void ldsm_x4(unsigned* r, const void* p)
{
    unsigned addr = (unsigned)__cvta_generic_to_shared(p);
    asm volatile("ldmatrix.sync.aligned.m8n8.x4.shared.b16 {%0,%1,%2,%3}, [%4];"
                 : "=r"(r[0]), "=r"(r[1]), "=r"(r[2]), "=r"(r[3]) : "r"(addr));
}
__device__ __forceinline__ void ldsm_x2(unsigned* r, const void* p)
{
    unsigned addr = (unsigned)__cvta_generic_to_shared(p);
    asm volatile("ldmatrix.sync.aligned.m8n8.x2.shared.b16 {%0,%1}, [%2];"
                 : "=r"(r[0]), "=r"(r[1]) : "r"(addr));
}
__device__ __forceinline__ void ldsm_x2t(unsigned* r, const void* p)
{
    unsigned addr = (unsigned)__cvta_generic_to_shared(p);
    asm volatile("ldmatrix.sync.aligned.m8n8.x2.trans.shared.b16 {%0,%1}, [%2];"
                 : "=r"(r[0]), "=r"(r[1]) : "r"(addr));
}

// ---------------- fp32 -> fp16 cast ----------------
__global__ __launch_bounds__(256) void cast16_kernel(
    const float* __restrict__ src, __half* __restrict__ dst, int n4)
{
    int i = blockIdx.x * blockDim.x + threadIdx.x;
    if (i >= n4) return;
    float4 x = ((const float4*)src)[i];
    __half2 h0 = __floats2half2_rn(x.x, x.y);
    __half2 h1 = __floats2half2_rn(x.z, x.w);
    ((__half2*)dst)[i * 2]     = h0;
    ((__half2*)dst)[i * 2 + 1] = h1;
}

// ---------------- fp32 -> fp16 hi/lo split ----------------
__global__ __launch_bounds__(256) void split16_kernel(
    const float* __restrict__ src,
    __half* __restrict__ hi, __half* __restrict__ lo, int n4)
{
    int i = blockIdx.x * blockDim.x + threadIdx.x;
    if (i >= n4) return;
    float4 x = ((const float4*)src)[i];
    __half h0 = __float2half_rn(x.x);
    __half h1 = __float2half_rn(x.y);
    __half h2 = __float2half_rn(x.z);
    __half h3 = __float2half_rn(x.w);
    __half l0 = __float2half_rn(x.x - __half2float(h0));
    __half l1 = __float2half_rn(x.y - __half2float(h1));
    __half l2 = __float2half_rn(x.z - __half2float(h2));
    __half l3 = __float2half_rn(x.w - __half2float(h3));
    ((__half2*)hi)[i * 2]     = __halves2half2(h0, h1);
    ((__half2*)hi)[i * 2 + 1] = __halves2half2(h2, h3);
    ((__half2*)lo)[i * 2]     = __halves2half2(l0, l1);
    ((__half2*)lo)[i * 2 + 1] = __halves2half2(l2, l3);
}

// ---------------- fp16x2 tensor-core GEMM, cp.async double-buffered ----------------
// C[M,N] = A[M,K] * (Bh+Bl)[N,K]^T + bias[N]
#define SPAD 40
#define GSTG (128 * SPAD)
#define GEMM_SMEM (6 * GSTG * 2)   // 3 arrays x 2 stages x 2B

__global__ __launch_bounds__(256, 2) void hgemm2(
    const __half* __restrict__ A,
    const __half* __restrict__ Bh, const __half* __restrict__ Bl,
    const float* __restrict__ bias, float* __restrict__ C,
    int M, int N, int K)
{
    extern __shared__ __half smg[];
    __half* sA  = smg;
    __half* sBh = smg + 2 * GSTG;
    __half* sBl = smg + 4 * GSTG;

    const int t    = threadIdx.x;
    const int lane = t & 31;
    const int warp = t >> 5;
    const int mw   = warp >> 2;
    const int nw   = warp & 3;
    const int bm   = blockIdx.y * 128;
    const int bn   = blockIdx.x * 128;

    const int lrow = t >> 1;
    const int lko  = (t & 1) * 16;
    const int soff = lrow * SPAD + lko;

    const size_t gA = (size_t)(bm + lrow) * K + lko;
    const size_t gB = (size_t)(bn + lrow) * K + lko;

    float acc[4][4][4];
#pragma unroll
    for (int i = 0; i < 4; i++)
#pragma unroll
        for (int j = 0; j < 4; j++)
#pragma unroll
            for (int e = 0; e < 4; e++) acc[i][j][e] = 0.0f;

    const int a_row = (lane & 15);
    const int a_col = (lane >> 4) * 8;
    const int b_row = (lane & 7);
    const int b_col = ((lane >> 3) & 1) * 8;

#define PREFETCH(k0, s) do {                                            \
        int st = (s) * GSTG;                                            \
        cp16(sA  + st + soff,     A  + gA + (k0));                      \
        cp16(sA  + st + soff + 8, A  + gA + (k0) + 8);                  \
        cp16(sBh + st + soff,     Bh + gB + (k0));                      \
        cp16(sBh + st + soff + 8, Bh + gB + (k0) + 8);                  \
        cp16(sBl + st + soff,     Bl + gB + (k0));                      \
        cp16(sBl + st + soff + 8, Bl + gB + (k0) + 8);                  \
    } while (0)

    PREFETCH(0, 0);
    asm volatile("cp.async.commit_group;");

    int s = 0;
    for (int k0 = 0; k0 < K; k0 += 32, s ^= 1) {
        if (k0 + 32 < K) {
            PREFETCH(k0 + 32, s ^ 1);
            asm volatile("cp.async.commit_group;");
            asm volatile("cp.async.wait_group 1;");
        } else {
            asm volatile("cp.async.wait_group 0;");
        }
        __syncthreads();

        const int st = s * GSTG;
#pragma unroll
        for (int ks = 0; ks < 32; ks += 16) {
            unsigned bh[4][2], bl[4][2], af[4][4];
#pragma unroll
            for (int nt = 0; nt < 4; nt++) {
                const int br = nw * 32 + nt * 8 + b_row;
                ldsm_x2(bh[nt], &sBh[st + br * SPAD + ks + b_col]);
                ldsm_x2(bl[nt], &sBl[st + br * SPAD + ks + b_col]);
            }
#pragma unroll
            for (int mt = 0; mt < 4; mt++) {
                const int ar = mw * 64 + mt * 16 + a_row;
                ldsm_x4(af[mt], &sA[st + ar * SPAD + ks + a_col]);
            }
#pragma unroll
            for (int mt = 0; mt < 4; mt++)
#pragma unroll
                for (int nt = 0; nt < 4; nt++) {
                    mma_f16(acc[mt][nt][0], acc[mt][nt][1], acc[mt][nt][2], acc[mt][nt][3],
                            af[mt][0], af[mt][1], af[mt][2], af[mt][3],
                            bh[nt][0], bh[nt][1]);
                    mma_f16(acc[mt][nt][0], acc[mt][nt][1], acc[mt][nt][2], acc[mt][nt][3],
                            af[mt][0], af[mt][1], af[mt][2], af[mt][3],
                            bl[nt][0], bl[nt][1]);
                }
        }
        __syncthreads();
    }

#pragma unroll
    for (int mt = 0; mt < 4; mt++) {
        const int r0 = bm + mw * 64 + mt * 16 + (lane >> 2);
        const int r1 = r0 + 8;
#pragma unroll
        for (int nt = 0; nt < 4; nt++) {
            const int c = bn + nw * 32 + nt * 8 + (lane & 3) * 2;
            const float bv0 = bias[c], bv1 = bias[c + 1];
            float2 o0 = {acc[mt][nt][0] + bv0, acc[mt][nt][1] + bv1};
            float2 o1 = {acc[mt][nt][2] + bv0, acc[mt][nt][3] + bv1};
            *(float2*)&C[(size_t)r0 * N + c] = o0;
            *(float2*)&C[(size_t)r1 * N + c] = o1;
        }
    }
}

// ---------------- RoPE + fp16 cast ----------------
__global__ __launch_bounds__(256) void rope_cast_kernel(
    const float* __restrict__ qkv,
    const float* __restrict__ cosp, const float* __restrict__ sinp,
    __half* __restrict__ q, __half* __restrict__ k, __half* __restrict__ v)
{
    int idx = blockIdx.x * blockDim.x + threadIdx.x;
    if (idx >= SEQ * NHEAD * 40) return;
    int d = idx % 40;
    int h = (idx / 40) % NHEAD;
    int s = idx / (40 * NHEAD);

    float c  = cosp[s * HD + d];
    float sn = sinp[s * HD + d];

    int base = s * QKVN + h * HD + d;
    float q1 = qkv[base],            q2 = qkv[base + 40];
    float k1 = qkv[base + HID],      k2 = qkv[base + HID + 40];
    float v1 = qkv[base + 2 * HID],  v2 = qkv[base + 2 * HID + 40];

    int o = (h * SEQ + s) * HD + d;
    q[o]      = __float2half(q1 * c - q2 * sn);
    q[o + 40] = __float2half(q2 * c + q1 * sn);
    k[o]      = __float2half(k1 * c - k2 * sn);
    k[o + 40] = __float2half(k2 * c + k1 * sn);
    v[o]      = __float2half(v1);
    v[o + 40] = __float2half(v2);
}

// ---------------- attention: fp16 tensor-core MMA ----------------
#define QPITCH 88
#define SPITCH 520
#define ATTN_SMEM ((128 * QPITCH + 128 * QPITCH + 128 * SPITCH) * 2 + 2 * 128 * 4)

__global__ __launch_bounds__(256) void attn_kernel(
    const __half* __restrict__ q, const __half* __restrict__ k,
    const __half* __restrict__ v, __half* __restrict__ attn_out)
{
    extern __shared__ char smraw[];
    __half* sQ   = (__half*)smraw;                     // [128][QPITCH]
    __half* sKV  = sQ + 128 * QPITCH;                  // [128][QPITCH]
    __half* Ss   = sKV + 128 * QPITCH;                 // [128][SPITCH]
    float*  mrow = (float*)(Ss + 128 * SPITCH);        // [128]
    float*  lrow = mrow + 128;

    const int tid  = threadIdx.x;
    const int lane = tid & 31;
    const int w    = tid >> 5;
    const int h    = blockIdx.y;
    const int seg  = blockIdx.x >> 2;
    const int qc   = blockIdx.x & 3;
    const int qbase = seg * SEGLEN + qc * 128;
    const int kbase = seg * SEGLEN;
    const float scale = 0.11180339887498949f;

    const int a_row = (lane & 15);
    const int a_col = (lane >> 4) * 8;
    const int b_row = (lane & 7);
    const int b_col = ((lane >> 3) & 1) * 8;

    for (int i = tid; i < 128 * 10; i += 256) {
        int r = i / 10, c8 = (i % 10) * 8;
        *(uint4*)&sQ[r * QPITCH + c8] =
            *(const uint4*)&q[(size_t)(h * SEQ + qbase + r) * HD + c8];
    }

    // ---- pass 1: scores ----
    for (int kt = 0; kt < 4; kt++) {
        __syncthreads();
        for (int i = tid; i < 128 * 10; i += 256) {
            int r = i / 10, c8 = (i % 10) * 8;
            *(uint4*)&sKV[r * QPITCH + c8] =
                *(const uint4*)&k[(size_t)(h * SEQ + kbase + kt * 128 + r) * HD + c8];
        }
        __syncthreads();

        float acc[16][4];
#pragma unroll
        for (int nt = 0; nt < 16; nt++)
#pragma unroll
            for (int e = 0; e < 4; e++) acc[nt][e] = 0.0f;

#pragma unroll
        for (int ks = 0; ks < 80; ks += 16) {
            unsigned af[4];
            ldsm_x4(af, &sQ[(w * 16 + a_row) * QPITCH + ks + a_col]);
#pragma unroll
            for (int nt = 0; nt < 16; nt++) {
                unsigned bf[2];
                ldsm_x2(bf, &sKV[(nt * 8 + b_row) * QPITCH + ks + b_col]);
                mma_f16(acc[nt][0], acc[nt][1], acc[nt][2], acc[nt][3],
                        af[0], af[1], af[2], af[3], bf[0], bf[1]);
            }
        }

        const int r0 = w * 16 + (lane >> 2);
#pragma unroll
        for (int nt = 0; nt < 16; nt++) {
            const int c = kt * 128 + nt * 8 + (lane & 3) * 2;
            *(__half2*)&Ss[r0 * SPITCH + c] =
                __floats2half2_rn(acc[nt][0] * scale, acc[nt][1] * scale);
            *(__half2*)&Ss[(r0 + 8) * SPITCH + c] =
                __floats2half2_rn(acc[nt][2] * scale, acc[nt][3] * scale);
        }
    }
    __syncthreads();

    // ---- softmax stats ----
    for (int rr = 0; rr < 16; rr++) {
        int r = w * 16 + rr;
        float m = -1e30f;
        for (int c = lane; c < 512; c += 32)
            m = fmaxf(m, __half2float(Ss[r * SPITCH + c]));
#pragma unroll
        for (int o = 16; o; o >>= 1)
            m = fmaxf(m, __shfl_xor_sync(0xffffffffu, m, o));
        float l = 0.0f;
        for (int c = lane; c < 512; c += 32)
            l += expf(__half2float(Ss[r * SPITCH + c]) - m);
#pragma unroll
        for (int o = 16; o; o >>= 1)
            l += __shfl_xor_sync(0xffffffffu, l, o);
        if (lane == 0) { mrow[r] = m; lrow[r] = l; }
    }
    __syncthreads();

    // ---- weights fp16 in place ----
    for (int i = tid; i < 128 * 512; i += 256) {
        int r = i >> 9, c = i & 511;
        float wgt = expf(__half2float(Ss[r * SPITCH + c]) - mrow[r]) / lrow[r];
        Ss[r * SPITCH + c] = __float2half(wgt);
    }

    // ---- pass 2: O = W @ V ----
    float oacc[10][4];
#pragma unroll
    for (int nt = 0; nt < 10; nt++)
#pragma unroll
        for (int e = 0; e < 4; e++) oacc[nt][e] = 0.0f;

    for (int kt = 0; kt < 4; kt++) {
        __syncthreads();
        for (int i = tid; i < 128 * 10; i += 256) {
            int r = i / 10, c8 = (i % 10) * 8;
            *(uint4*)&sKV[r * QPITCH + c8] =
                *(const uint4*)&v[(size_t)(h * SEQ + kbase + kt * 128 + r) * HD + c8];
        }
        __syncthreads();

#pragma unroll
        for (int ks = 0; ks < 8; ks++) {
            unsigned af[4];
            ldsm_x4(af, &Ss[(w * 16 + a_row) * SPITCH + kt * 128 + ks * 16 + a_col]);
#pragma unroll
            for (int nt = 0; nt < 10; nt++) {
                unsigned bf[2];
                ldsm_x2t(bf, &sKV[(ks * 16 + (lane & 15)) * QPITCH + nt * 8]);
                mma_f16(oacc[nt][0], oacc[nt][1], oacc[nt][2], oacc[nt][3],
                        af[0], af[1], af[2], af[3], bf[0], bf[1]);
            }
        }
    }

    // write out as fp16 (exactly what the reference's attn output is)
    const int r0 = qbase + w * 16 + (lane >> 2);
#pragma unroll
    for (int nt = 0; nt < 10; nt++) {
        const int c = h * HD + nt * 8 + (lane & 3) * 2;
        *(__half2*)&attn_out[(size_t)r0 * HID + c] =
            __floats2half2_rn(oacc[nt][0], oacc[nt][1]);
        *(__half2*)&attn_out[(size_t)(r0 + 8) * HID + c] =
            __floats2half2_rn(oacc[nt][2], oacc[nt][3]);
    }
}

// ---------------- launch ----------------
extern "C" void kernel_launch(void* const* d_in, const int* in_sizes, int n_in,
                              void* d_out, int out_size)
{
    const float* hidden = (const float*)d_in[0];
    const float* cosp   = (const float*)d_in[1];
    const float* sinp   = (const float*)d_in[2];
    const float* w_qkv  = (const float*)d_in[3];
    const float* b_qkv  = (const float*)d_in[4];
    const float* w_proj = (const float*)d_in[5];
    const float* b_proj = (const float*)d_in[6];
    float* out = (float*)d_out;

    float *qkv_p;
    __half *q_p, *k_p, *v_p, *attn16_p, *a16_p, *wqkv_h, *wqkv_l, *wpr_h, *wpr_l;
    cudaGetSymbolAddress((void**)&qkv_p, g_qkv);
    cudaGetSymbolAddress((void**)&q_p, g_q);
    cudaGetSymbolAddress((void**)&k_p, g_k);
    cudaGetSymbolAddress((void**)&v_p, g_v);
    cudaGetSymbolAddress((void**)&attn16_p, g_attn16);
    cudaGetSymbolAddress((void**)&a16_p, g_a16);
    cudaGetSymbolAddress((void**)&wqkv_h, g_wqkv_hi);
    cudaGetSymbolAddress((void**)&wqkv_l, g_wqkv_lo);
    cudaGetSymbolAddress((void**)&wpr_h, g_wpr_hi);
    cudaGetSymbolAddress((void**)&wpr_l, g_wpr_lo);

    cudaFuncSetAttribute(attn_kernel,
                         cudaFuncAttributeMaxDynamicSharedMemorySize, ATTN_SMEM);
    cudaFuncSetAttribute(hgemm2,
                         cudaFuncAttributeMaxDynamicSharedMemorySize, GEMM_SMEM);

    // 0) cast hidden to fp16; split weights to fp16 hi/lo
    cast16_kernel<<<(SEQ * HID / 4 + 255) / 256, 256>>>(hidden, a16_p, SEQ * HID / 4);
    split16_kernel<<<(QKVN * HID / 4 + 255) / 256, 256>>>(w_qkv, wqkv_h, wqkv_l, QKVN * HID / 4);
    split16_kernel<<<(HID * HID / 4 + 255) / 256, 256>>>(w_proj, wpr_h, wpr_l, HID * HID / 4);

    // 1) QKV GEMM (fp16 x2)
    hgemm2<<<dim3(QKVN / 128, SEQ / 128), 256, GEMM_SMEM>>>(
        a16_p, wqkv_h, wqkv_l, b_qkv, qkv_p, SEQ, QKVN, HID);

    // 2) RoPE + fp16 cast
    rope_cast_kernel<<<(SEQ * NHEAD * 40) / 256, 256>>>(
        qkv_p, cosp, sinp, q_p, k_p, v_p);

    // 3) block-diagonal attention (tensor cores), fp16 output
    attn_kernel<<<dim3(NSEG * 4, NHEAD), 256, ATTN_SMEM>>>(
        q_p, k_p, v_p, attn16_p);

    // 4) proj GEMM (fp16 x2, A exact fp16)
    hgemm2<<<dim3(HID / 128, SEQ / 128), 256, GEMM_SMEM>>>(
        attn16_p, wpr_h, wpr_l, b_proj, out, SEQ, HID, HID);
}

// round 5
// speedup vs baseline: 4.2107x; 1.3211x over previous
#include <cuda_runtime.h>
#include <cuda_fp16.h>

#define SEQ    3072
#define HID    1280
#define NHEAD  16
#define HD     80
#define SEGLEN 512
#define NSEG   6
#define QKVN   3840

// ---------------- scratch (no allocations allowed) ----------------
__device__ float  g_qkv[SEQ * QKVN];
__device__ __half g_q[NHEAD * SEQ * HD];       // [h][s][d]
__device__ __half g_k[NHEAD * SEQ * HD];
__device__ __half g_v[NHEAD * SEQ * HD];
__device__ __half g_attn16[SEQ * HID];         // attention output, exact fp16

__device__ __half g_a16[SEQ * HID];            // hidden cast to fp16
__device__ __half g_wqkv16[QKVN * HID];        // w_qkv cast to fp16
__device__ __half g_wpr_hi[HID * HID], g_wpr_lo[HID * HID];

// ---------------- helpers ----------------
__device__ __forceinline__ void cp16(void* dst, const void* src)
{
    unsigned d = (unsigned)__cvta_generic_to_shared(dst);
    asm volatile("cp.async.cg.shared.global [%0], [%1], 16;" :: "r"(d), "l"(src));
}

__device__ __forceinline__ void mma_f16(
    float& c0, float& c1, float& c2, float& c3,
    unsigned a0, unsigned a1, unsigned a2, unsigned a3,
    unsigned b0, unsigned b1)
{
    asm volatile(
        "mma.sync.aligned.m16n8k16.row.col.f32.f16.f16.f32 "
        "{%0,%1,%2,%3}, {%4,%5,%6,%7}, {%8,%9}, {%0,%1,%2,%3};"
        : "+f"(c0), "+f"(c1), "+f"(c2), "+f"(c3)
        : "r"(a0), "r"(a1), "r"(a2), "r"(a3), "r"(b0), "r"(b1));
}

__device__ __forceinline__ void ldsm_x4(unsigned* r, const void* p)
{
    unsigned addr = (unsigned)__cvta_generic_to_shared(p);
    asm volatile("ldmatrix.sync.aligned.m8n8.x4.shared.b16 {%0,%1,%2,%3}, [%4];"
                 : "=r"(r[0]), "=r"(r[1]), "=r"(r[2]), "=r"(r[3]) : "r"(addr));
}
__device__ __forceinline__ void ldsm_x4t(unsigned* r, const void* p)
{
    unsigned addr = (unsigned)__cvta_generic_to_shared(p);
    asm volatile("ldmatrix.sync.aligned.m8n8.x4.trans.shared.b16 {%0,%1,%2,%3}, [%4];"
                 : "=r"(r[0]), "=r"(r[1]), "=r"(r[2]), "=r"(r[3]) : "r"(addr));
}

// ---------------- casts / splits ----------------
__global__ __launch_bounds__(256) void cast16_kernel(
    const float* __restrict__ src, __half* __restrict__ dst, int n4)
{
    int i = blockIdx.x * blockDim.x + threadIdx.x;
    if (i >= n4) return;
    float4 x = ((const float4*)src)[i];
    ((__half2*)dst)[i * 2]     = __floats2half2_rn(x.x, x.y);
    ((__half2*)dst)[i * 2 + 1] = __floats2half2_rn(x.z, x.w);
}

__global__ __launch_bounds__(256) void split16_kernel(
    const float* __restrict__ src,
    __half* __restrict__ hi, __half* __restrict__ lo, int n4)
{
    int i = blockIdx.x * blockDim.x + threadIdx.x;
    if (i >= n4) return;
    float4 x = ((const float4*)src)[i];
    __half h0 = __float2half_rn(x.x), h1 = __float2half_rn(x.y);
    __half h2 = __float2half_rn(x.z), h3 = __float2half_rn(x.w);
    __half l0 = __float2half_rn(x.x - __half2float(h0));
    __half l1 = __float2half_rn(x.y - __half2float(h1));
    __half l2 = __float2half_rn(x.z - __half2float(h2));
    __half l3 = __float2half_rn(x.w - __half2float(h3));
    ((__half2*)hi)[i * 2]     = __halves2half2(h0, h1);
    ((__half2*)hi)[i * 2 + 1] = __halves2half2(h2, h3);
    ((__half2*)lo)[i * 2]     = __halves2half2(l0, l1);
    ((__half2*)lo)[i * 2 + 1] = __halves2half2(l2, l3);
}

// ---------------- GEMM shared config ----------------
#define SPAD 40
#define GSTG (128 * SPAD)

// ---------------- hgemm1: C = A * B^T + bias (single-pass fp16) ----------------
#define GEMM1_SMEM (4 * GSTG * 2)   // 2 arrays x 2 stages x 2B

__global__ __launch_bounds__(256, 2) void hgemm1(
    const __half* __restrict__ A, const __half* __restrict__ B,
    const float* __restrict__ bias, float* __restrict__ C,
    int M, int N, int K)
{
    extern __shared__ __half smg[];
    __half* sA = smg;
    __half* sB = smg + 2 * GSTG;

    const int t    = threadIdx.x;
    const int lane = t & 31;
    const int warp = t >> 5;
    const int mw   = warp >> 2;
    const int nw   = warp & 3;
    const int bm   = blockIdx.y * 128;
    const int bn   = blockIdx.x * 128;

    const int lrow = t >> 1;
    const int lko  = (t & 1) * 16;
    const int soff = lrow * SPAD + lko;

    const size_t gA = (size_t)(bm + lrow) * K + lko;
    const size_t gB = (size_t)(bn + lrow) * K + lko;

    float acc[4][4][4];
#pragma unroll
    for (int i = 0; i < 4; i++)
#pragma unroll
        for (int j = 0; j < 4; j++)
#pragma unroll
            for (int e = 0; e < 4; e++) acc[i][j][e] = 0.0f;

    const int a_row  = (lane & 15);
    const int a_col  = (lane >> 4) * 8;
    const int b_row4 = (lane & 7) + ((lane >> 4) & 1) * 8;
    const int b_col4 = ((lane >> 3) & 1) * 8;

#define PF1(k0, s) do {                                                 \
        int st = (s) * GSTG;                                            \
        cp16(sA + st + soff,     A + gA + (k0));                        \
        cp16(sA + st + soff + 8, A + gA + (k0) + 8);                    \
        cp16(sB + st + soff,     B + gB + (k0));                        \
        cp16(sB + st + soff + 8, B + gB + (k0) + 8);                    \
    } while (0)

    PF1(0, 0);
    asm volatile("cp.async.commit_group;");

    int s = 0;
    for (int k0 = 0; k0 < K; k0 += 32, s ^= 1) {
        if (k0 + 32 < K) {
            PF1(k0 + 32, s ^ 1);
            asm volatile("cp.async.commit_group;");
            asm volatile("cp.async.wait_group 1;");
        } else {
            asm volatile("cp.async.wait_group 0;");
        }
        __syncthreads();

        const int st = s * GSTG;
#pragma unroll
        for (int ks = 0; ks < 32; ks += 16) {
            unsigned af[4][4], bq[2][4];
#pragma unroll
            for (int p = 0; p < 2; p++)
                ldsm_x4(bq[p], &sB[st + (nw * 32 + p * 16 + b_row4) * SPAD + ks + b_col4]);
#pragma unroll
            for (int mt = 0; mt < 4; mt++)
                ldsm_x4(af[mt], &sA[st + (mw * 64 + mt * 16 + a_row) * SPAD + ks + a_col]);
#pragma unroll
            for (int mt = 0; mt < 4; mt++)
#pragma unroll
                for (int p = 0; p < 2; p++) {
                    mma_f16(acc[mt][2*p][0], acc[mt][2*p][1], acc[mt][2*p][2], acc[mt][2*p][3],
                            af[mt][0], af[mt][1], af[mt][2], af[mt][3],
                            bq[p][0], bq[p][1]);
                    mma_f16(acc[mt][2*p+1][0], acc[mt][2*p+1][1], acc[mt][2*p+1][2], acc[mt][2*p+1][3],
                            af[mt][0], af[mt][1], af[mt][2], af[mt][3],
                            bq[p][2], bq[p][3]);
                }
        }
        __syncthreads();
    }

#pragma unroll
    for (int mt = 0; mt < 4; mt++) {
        const int r0 = bm + mw * 64 + mt * 16 + (lane >> 2);
        const int r1 = r0 + 8;
#pragma unroll
        for (int nt = 0; nt < 4; nt++) {
            const int c = bn + nw * 32 + nt * 8 + (lane & 3) * 2;
            const float bv0 = bias[c], bv1 = bias[c + 1];
            float2 o0 = {acc[mt][nt][0] + bv0, acc[mt][nt][1] + bv1};
            float2 o1 = {acc[mt][nt][2] + bv0, acc[mt][nt][3] + bv1};
            *(float2*)&C[(size_t)r0 * N + c] = o0;
            *(float2*)&C[(size_t)r1 * N + c] = o1;
        }
    }
}

// ---------------- hgemm2: C = A * (Bh+Bl)^T + bias (exact) ----------------
#define GEMM2_SMEM (6 * GSTG * 2)

__global__ __launch_bounds__(256, 2) void hgemm2(
    const __half* __restrict__ A,
    const __half* __restrict__ Bh, const __half* __restrict__ Bl,
    const float* __restrict__ bias, float* __restrict__ C,
    int M, int N, int K)
{
    extern __shared__ __half smg[];
    __half* sA  = smg;
    __half* sBh = smg + 2 * GSTG;
    __half* sBl = smg + 4 * GSTG;

    const int t    = threadIdx.x;
    const int lane = t & 31;
    const int warp = t >> 5;
    const int mw   = warp >> 2;
    const int nw   = warp & 3;
    const int bm   = blockIdx.y * 128;
    const int bn   = blockIdx.x * 128;

    const int lrow = t >> 1;
    const int lko  = (t & 1) * 16;
    const int soff = lrow * SPAD + lko;

    const size_t gA = (size_t)(bm + lrow) * K + lko;
    const size_t gB = (size_t)(bn + lrow) * K + lko;

    float acc[4][4][4];
#pragma unroll
    for (int i = 0; i < 4; i++)
#pragma unroll
        for (int j = 0; j < 4; j++)
#pragma unroll
            for (int e = 0; e < 4; e++) acc[i][j][e] = 0.0f;

    const int a_row  = (lane & 15);
    const int a_col  = (lane >> 4) * 8;
    const int b_row4 = (lane & 7) + ((lane >> 4) & 1) * 8;
    const int b_col4 = ((lane >> 3) & 1) * 8;

#define PF2(k0, s) do {                                                 \
        int st = (s) * GSTG;                                            \
        cp16(sA  + st + soff,     A  + gA + (k0));                      \
        cp16(sA  + st + soff + 8, A  + gA + (k0) + 8);                  \
        cp16(sBh + st + soff,     Bh + gB + (k0));                      \
        cp16(sBh + st + soff + 8, Bh + gB + (k0) + 8);                  \
        cp16(sBl + st + soff,     Bl + gB + (k0));                      \
        cp16(sBl + st + soff + 8, Bl + gB + (k0) + 8);                  \
    } while (0)

    PF2(0, 0);
    asm volatile("cp.async.commit_group;");

    int s = 0;
    for (int k0 = 0; k0 < K; k0 += 32, s ^= 1) {
        if (k0 + 32 < K) {
            PF2(k0 + 32, s ^ 1);
            asm volatile("cp.async.commit_group;");
            asm volatile("cp.async.wait_group 1;");
        } else {
            asm volatile("cp.async.wait_group 0;");
        }
        __syncthreads();

        const int st = s * GSTG;
#pragma unroll
        for (int ks = 0; ks < 32; ks += 16) {
            unsigned af[4][4], bh[2][4], bl[2][4];
#pragma unroll
            for (int p = 0; p < 2; p++) {
                const int br = (nw * 32 + p * 16 + b_row4) * SPAD + ks + b_col4;
                ldsm_x4(bh[p], &sBh[st + br]);
                ldsm_x4(bl[p], &sBl[st + br]);
            }
#pragma unroll
            for (int mt = 0; mt < 4; mt++)
                ldsm_x4(af[mt], &sA[st + (mw * 64 + mt * 16 + a_row) * SPAD + ks + a_col]);
#pragma unroll
            for (int mt = 0; mt < 4; mt++)
#pragma unroll
                for (int p = 0; p < 2; p++) {
                    mma_f16(acc[mt][2*p][0], acc[mt][2*p][1], acc[mt][2*p][2], acc[mt][2*p][3],
                            af[mt][0], af[mt][1], af[mt][2], af[mt][3],
                            bh[p][0], bh[p][1]);
                    mma_f16(acc[mt][2*p][0], acc[mt][2*p][1], acc[mt][2*p][2], acc[mt][2*p][3],
                            af[mt][0], af[mt][1], af[mt][2], af[mt][3],
                            bl[p][0], bl[p][1]);
                    mma_f16(acc[mt][2*p+1][0], acc[mt][2*p+1][1], acc[mt][2*p+1][2], acc[mt][2*p+1][3],
                            af[mt][0], af[mt][1], af[mt][2], af[mt][3],
                            bh[p][2], bh[p][3]);
                    mma_f16(acc[mt][2*p+1][0], acc[mt][2*p+1][1], acc[mt][2*p+1][2], acc[mt][2*p+1][3],
                            af[mt][0], af[mt][1], af[mt][2], af[mt][3],
                            bl[p][2], bl[p][3]);
                }
        }
        __syncthreads();
    }

#pragma unroll
    for (int mt = 0; mt < 4; mt++) {
        const int r0 = bm + mw * 64 + mt * 16 + (lane >> 2);
        const int r1 = r0 + 8;
#pragma unroll
        for (int nt = 0; nt < 4; nt++) {
            const int c = bn + nw * 32 + nt * 8 + (lane & 3) * 2;
            const float bv0 = bias[c], bv1 = bias[c + 1];
            float2 o0 = {acc[mt][nt][0] + bv0, acc[mt][nt][1] + bv1};
            float2 o1 = {acc[mt][nt][2] + bv0, acc[mt][nt][3] + bv1};
            *(float2*)&C[(size_t)r0 * N + c] = o0;
            *(float2*)&C[(size_t)r1 * N + c] = o1;
        }
    }
}

// ---------------- RoPE + fp16 cast ----------------
__global__ __launch_bounds__(256) void rope_cast_kernel(
    const float* __restrict__ qkv,
    const float* __restrict__ cosp, const float* __restrict__ sinp,
    __half* __restrict__ q, __half* __restrict__ k, __half* __restrict__ v)
{
    int idx = blockIdx.x * blockDim.x + threadIdx.x;
    if (idx >= SEQ * NHEAD * 40) return;
    int d = idx % 40;
    int h = (idx / 40) % NHEAD;
    int s = idx / (40 * NHEAD);

    float c  = cosp[s * HD + d];
    float sn = sinp[s * HD + d];

    int base = s * QKVN + h * HD + d;
    float q1 = qkv[base],            q2 = qkv[base + 40];
    float k1 = qkv[base + HID],      k2 = qkv[base + HID + 40];
    float v1 = qkv[base + 2 * HID],  v2 = qkv[base + 2 * HID + 40];

    int o = (h * SEQ + s) * HD + d;
    q[o]      = __float2half(q1 * c - q2 * sn);
    q[o + 40] = __float2half(q2 * c + q1 * sn);
    k[o]      = __float2half(k1 * c - k2 * sn);
    k[o + 40] = __float2half(k2 * c + k1 * sn);
    v[o]      = __float2half(v1);
    v[o + 40] = __float2half(v2);
}

// ---------------- attention: fp16 MMA, cp.async double-buffered KV ----------------
#define QPITCH 88
#define SPITCH 520
#define KVTILE (128 * QPITCH)
#define ATTN_SMEM ((KVTILE * 3 + 128 * SPITCH) * 2 + 2 * 128 * 4)

__global__ __launch_bounds__(256) void attn_kernel(
    const __half* __restrict__ q, const __half* __restrict__ k,
    const __half* __restrict__ v, __half* __restrict__ attn_out)
{
    extern __shared__ char smraw[];
    __half* sQ   = (__half*)smraw;                 // [128][QPITCH]
    __half* sKV0 = sQ + KVTILE;
    __half* sKV1 = sKV0 + KVTILE;
    __half* Ss   = sKV1 + KVTILE;                  // [128][SPITCH]
    float*  mrow = (float*)(Ss + 128 * SPITCH);
    float*  lrow = mrow + 128;

    const int tid  = threadIdx.x;
    const int lane = tid & 31;
    const int w    = tid >> 5;
    const int h    = blockIdx.y;
    const int seg  = blockIdx.x >> 2;
    const int qc   = blockIdx.x & 3;
    const int qbase = seg * SEGLEN + qc * 128;
    const int kbase = seg * SEGLEN;
    const float scale = 0.11180339887498949f;

    const int a_row  = (lane & 15);
    const int a_col  = (lane >> 4) * 8;
    const int b_row4 = (lane & 7) + ((lane >> 4) & 1) * 8;
    const int b_col4 = ((lane >> 3) & 1) * 8;

    // async load Q + K tile 0 (group 0)
    for (int i = tid; i < 1280; i += 256) {
        int r = i / 10, c8 = (i % 10) * 8;
        cp16(&sQ[r * QPITCH + c8], &q[(size_t)(h * SEQ + qbase + r) * HD + c8]);
        cp16(&sKV0[r * QPITCH + c8], &k[(size_t)(h * SEQ + kbase + r) * HD + c8]);
    }
    asm volatile("cp.async.commit_group;");

    // ---- pass 1: scores ----
    for (int kt = 0; kt < 4; kt++) {
        __half* cur = (kt & 1) ? sKV1 : sKV0;
        __half* nxt = (kt & 1) ? sKV0 : sKV1;
        if (kt < 3) {
            for (int i = tid; i < 1280; i += 256) {
                int r = i / 10, c8 = (i % 10) * 8;
                cp16(&nxt[r * QPITCH + c8],
                     &k[(size_t)(h * SEQ + kbase + (kt + 1) * 128 + r) * HD + c8]);
            }
            asm volatile("cp.async.commit_group;");
            asm volatile("cp.async.wait_group 1;");
        } else {
            asm volatile("cp.async.wait_group 0;");
        }
        __syncthreads();

        float acc[16][4];
#pragma unroll
        for (int nt = 0; nt < 16; nt++)
#pragma unroll
            for (int e = 0; e < 4; e++) acc[nt][e] = 0.0f;

#pragma unroll
        for (int ks = 0; ks < 80; ks += 16) {
            unsigned af[4];
            ldsm_x4(af, &sQ[(w * 16 + a_row) * QPITCH + ks + a_col]);
#pragma unroll
            for (int p = 0; p < 8; p++) {
                unsigned bq[4];
                ldsm_x4(bq, &cur[(p * 16 + b_row4) * QPITCH + ks + b_col4]);
                mma_f16(acc[2*p][0], acc[2*p][1], acc[2*p][2], acc[2*p][3],
                        af[0], af[1], af[2], af[3], bq[0], bq[1]);
                mma_f16(acc[2*p+1][0], acc[2*p+1][1], acc[2*p+1][2], acc[2*p+1][3],
                        af[0], af[1], af[2], af[3], bq[2], bq[3]);
            }
        }

        const int r0 = w * 16 + (lane >> 2);
#pragma unroll
        for (int nt = 0; nt < 16; nt++) {
            const int c = kt * 128 + nt * 8 + (lane & 3) * 2;
            *(__half2*)&Ss[r0 * SPITCH + c] =
                __floats2half2_rn(acc[nt][0] * scale, acc[nt][1] * scale);
            *(__half2*)&Ss[(r0 + 8) * SPITCH + c] =
                __floats2half2_rn(acc[nt][2] * scale, acc[nt][3] * scale);
        }
        __syncthreads();
    }

    // prefetch V tile 0 (overlaps softmax)
    for (int i = tid; i < 1280; i += 256) {
        int r = i / 10, c8 = (i % 10) * 8;
        cp16(&sKV0[r * QPITCH + c8], &v[(size_t)(h * SEQ + kbase + r) * HD + c8]);
    }
    asm volatile("cp.async.commit_group;");

    // ---- softmax stats ----
    for (int rr = 0; rr < 16; rr++) {
        int r = w * 16 + rr;
        float m = -1e30f;
        for (int c = lane; c < 512; c += 32)
            m = fmaxf(m, __half2float(Ss[r * SPITCH + c]));
#pragma unroll
        for (int o = 16; o; o >>= 1)
            m = fmaxf(m, __shfl_xor_sync(0xffffffffu, m, o));
        float l = 0.0f;
        for (int c = lane; c < 512; c += 32)
            l += expf(__half2float(Ss[r * SPITCH + c]) - m);
#pragma unroll
        for (int o = 16; o; o >>= 1)
            l += __shfl_xor_sync(0xffffffffu, l, o);
        if (lane == 0) { mrow[r] = m; lrow[r] = l; }
    }
    __syncthreads();

    // ---- weights fp16 in place ----
    for (int i = tid; i < 128 * 512; i += 256) {
        int r = i >> 9, c = i & 511;
        float wgt = expf(__half2float(Ss[r * SPITCH + c]) - mrow[r]) / lrow[r];
        Ss[r * SPITCH + c] = __float2half(wgt);
    }

    // ---- pass 2: O = W @ V ----
    float oacc[10][4];
#pragma unroll
    for (int nt = 0; nt < 10; nt++)
#pragma unroll
        for (int e = 0; e < 4; e++) oacc[nt][e] = 0.0f;

    for (int kt = 0; kt < 4; kt++) {
        __half* cur = (kt & 1) ? sKV1 : sKV0;
        __half* nxt = (kt & 1) ? sKV0 : sKV1;
        if (kt < 3) {
            for (int i = tid; i < 1280; i += 256) {
                int r = i / 10, c8 = (i % 10) * 8;
                cp16(&nxt[r * QPITCH + c8],
                     &v[(size_t)(h * SEQ + kbase + (kt + 1) * 128 + r) * HD + c8]);
            }
            asm volatile("cp.async.commit_group;");
            asm volatile("cp.async.wait_group 1;");
        } else {
            asm volatile("cp.async.wait_group 0;");
        }
        __syncthreads();

#pragma unroll
        for (int ks = 0; ks < 8; ks++) {
            unsigned af[4];
            ldsm_x4(af, &Ss[(w * 16 + a_row) * SPITCH + kt * 128 + ks * 16 + a_col]);
#pragma unroll
            for (int p = 0; p < 5; p++) {
                unsigned bq[4];
                ldsm_x4t(bq, &cur[(ks * 16 + (lane & 15)) * QPITCH
                                  + p * 16 + ((lane >> 4) & 1) * 8]);
                mma_f16(oacc[2*p][0], oacc[2*p][1], oacc[2*p][2], oacc[2*p][3],
                        af[0], af[1], af[2], af[3], bq[0], bq[1]);
                mma_f16(oacc[2*p+1][0], oacc[2*p+1][1], oacc[2*p+1][2], oacc[2*p+1][3],
                        af[0], af[1], af[2], af[3], bq[2], bq[3]);
            }
        }
        __syncthreads();
    }

    // write out as fp16 (exact match of reference attn output dtype)
    const int r0 = qbase + w * 16 + (lane >> 2);
#pragma unroll
    for (int nt = 0; nt < 10; nt++) {
        const int c = h * HD + nt * 8 + (lane & 3) * 2;
        *(__half2*)&attn_out[(size_t)r0 * HID + c] =
            __floats2half2_rn(oacc[nt][0], oacc[nt][1]);
        *(__half2*)&attn_out[(size_t)(r0 + 8) * HID + c] =
            __floats2half2_rn(oacc[nt][2], oacc[nt][3]);
    }
}

// ---------------- launch ----------------
extern "C" void kernel_launch(void* const* d_in, const int* in_sizes, int n_in,
                              void* d_out, int out_size)
{
    const float* hidden = (const float*)d_in[0];
    const float* cosp   = (const float*)d_in[1];
    const float* sinp   = (const float*)d_in[2];
    const float* w_qkv  = (const float*)d_in[3];
    const float* b_qkv  = (const float*)d_in[4];
    const float* w_proj = (const float*)d_in[5];
    const float* b_proj = (const float*)d_in[6];
    float* out = (float*)d_out;

    float *qkv_p;
    __half *q_p, *k_p, *v_p, *attn16_p, *a16_p, *wqkv16_p, *wpr_h, *wpr_l;
    cudaGetSymbolAddress((void**)&qkv_p, g_qkv);
    cudaGetSymbolAddress((void**)&q_p, g_q);
    cudaGetSymbolAddress((void**)&k_p, g_k);
    cudaGetSymbolAddress((void**)&v_p, g_v);
    cudaGetSymbolAddress((void**)&attn16_p, g_attn16);
    cudaGetSymbolAddress((void**)&a16_p, g_a16);
    cudaGetSymbolAddress((void**)&wqkv16_p, g_wqkv16);
    cudaGetSymbolAddress((void**)&wpr_h, g_wpr_hi);
    cudaGetSymbolAddress((void**)&wpr_l, g_wpr_lo);

    cudaFuncSetAttribute(attn_kernel,
                         cudaFuncAttributeMaxDynamicSharedMemorySize, ATTN_SMEM);
    cudaFuncSetAttribute(hgemm1,
                         cudaFuncAttributeMaxDynamicSharedMemorySize, GEMM1_SMEM);
    cudaFuncSetAttribute(hgemm2,
                         cudaFuncAttributeMaxDynamicSharedMemorySize, GEMM2_SMEM);

    // 0) casts / splits
    cast16_kernel<<<(SEQ * HID / 4 + 255) / 256, 256>>>(hidden, a16_p, SEQ * HID / 4);
    cast16_kernel<<<(QKVN * HID / 4 + 255) / 256, 256>>>(w_qkv, wqkv16_p, QKVN * HID / 4);
    split16_kernel<<<(HID * HID / 4 + 255) / 256, 256>>>(w_proj, wpr_h, wpr_l, HID * HID / 4);

    // 1) QKV GEMM (single-pass fp16)
    hgemm1<<<dim3(QKVN / 128, SEQ / 128), 256, GEMM1_SMEM>>>(
        a16_p, wqkv16_p, b_qkv, qkv_p, SEQ, QKVN, HID);

    // 2) RoPE + fp16 cast
    rope_cast_kernel<<<(SEQ * NHEAD * 40) / 256, 256>>>(
        qkv_p, cosp, sinp, q_p, k_p, v_p);

    // 3) block-diagonal attention
    attn_kernel<<<dim3(NSEG * 4, NHEAD), 256, ATTN_SMEM>>>(
        q_p, k_p, v_p, attn16_p);

    // 4) proj GEMM (exact: A fp16, B hi/lo)
    hgemm2<<<dim3(HID / 128, SEQ / 128), 256, GEMM2_SMEM>>>(
        attn16_p, wpr_h, wpr_l, b_proj, out, SEQ, HID, HID);
}